// round 8
// baseline (speedup 1.0000x reference)
#include <cuda_runtime.h>
#include <math.h>
#include <stdint.h>

#define N_DIM 4096
#define B_DIM 512
#define NB 128
#define NPAN (N_DIM / NB)

// ---------------- device scratch ------------------------------------------
__device__ float g_M[(size_t)N_DIM * N_DIM];   // 64 MB: M -> L -> F(lower)/G(upper)
__device__ float g_Linv[NPAN * NB * NB];       // 2 MB: diag-block inverses
__device__ float g_X1[(size_t)B_DIM * N_DIM];  // 8 MB workspaces
__device__ float g_X2[(size_t)B_DIM * N_DIM];
__device__ float g_X3[(size_t)B_DIM * N_DIM];
__device__ float g_scal[4];                    // c1, c2
__device__ int g_flag[NPAN];                   // diag-done flags (per replay)

// ---------------- scalars + flag reset ------------------------------------
__global__ void scalars_kernel(const float* __restrict__ imp,
                               const float* __restrict__ exc,
                               const float* __restrict__ gamma_p) {
    __shared__ float red[32];
    int tid = threadIdx.x;  // 1024
    if (tid < NPAN) g_flag[tid] = 0;
    float v = imp[tid] * imp[tid] + exc[tid] * exc[tid];
    #pragma unroll
    for (int o = 16; o > 0; o >>= 1) v += __shfl_down_sync(0xffffffffu, v, o);
    if ((tid & 31) == 0) red[tid >> 5] = v;
    __syncthreads();
    if (tid < 32) {
        float s = red[tid];
        #pragma unroll
        for (int o = 16; o > 0; o >>= 1) s += __shfl_down_sync(0xffffffffu, s, o);
        if (tid == 0) {
            g_scal[0] = s / (float)B_DIM;
            g_scal[1] = gamma_p[0] / (float)B_DIM;
        }
    }
}

// ---------------- build M = c1*Phi + c2*I ---------------------------------
__global__ void build_M_kernel(const float* __restrict__ Phi) {
    const float c1 = g_scal[0], c2 = g_scal[1];
    size_t total = (size_t)N_DIM * N_DIM;
    for (size_t i = (size_t)blockIdx.x * blockDim.x + threadIdx.x; i < total;
         i += (size_t)gridDim.x * blockDim.x) {
        float v = c1 * Phi[i];
        if ((i >> 12) == (i & 4095)) v += c2;
        g_M[i] = v;
    }
}

__global__ void copy_kernel(float* __restrict__ dst, const float* __restrict__ src,
                            size_t n4) {
    for (size_t i = (size_t)blockIdx.x * blockDim.x + threadIdx.x; i < n4;
         i += (size_t)gridDim.x * blockDim.x) {
        reinterpret_cast<float4*>(dst)[i] = reinterpret_cast<const float4*>(src)[i];
    }
}

// ---------------- double-buffered 128-wide GEMM microkernel ----------------
// A pre-offset to tile row start; B pre-offset to tile col start.
// BT=1: acc += A(128xK) * B(128xK)^T ; BT=0: acc += A(128xK) * B(Kx128).
// K multiple of 16.  256 threads.  One barrier per 16-K step.
template <int BT>
__device__ __forceinline__ void gemm_db(const float* __restrict__ A, int lda,
                                        const float* __restrict__ B, int ldb,
                                        float acc[8][8], int K) {
    __shared__ float As[2][16][132];
    __shared__ float Bs[2][16][132];
    const int tid = threadIdx.x;
    const int ai = tid >> 1;
    const int aw = (tid & 1) << 3;
    const int br = tid >> 5;            // BT=0 load row helper
    const int bc = (tid & 31) << 2;     // BT=0 load col helper
    const int ty = tid >> 4, tx = tid & 15;

    float4 av0, av1, bv0, bv1;
    // prologue: load k0 = 0
    av0 = *reinterpret_cast<const float4*>(&A[(size_t)ai * lda + aw]);
    av1 = *reinterpret_cast<const float4*>(&A[(size_t)ai * lda + aw + 4]);
    if (BT) {
        bv0 = *reinterpret_cast<const float4*>(&B[(size_t)ai * ldb + aw]);
        bv1 = *reinterpret_cast<const float4*>(&B[(size_t)ai * ldb + aw + 4]);
    } else {
        bv0 = *reinterpret_cast<const float4*>(&B[(size_t)br * ldb + bc]);
        bv1 = *reinterpret_cast<const float4*>(&B[(size_t)(br + 8) * ldb + bc]);
    }
    {
        float (*Aw)[132] = As[0];
        float (*Bw)[132] = Bs[0];
        Aw[aw + 0][ai] = av0.x; Aw[aw + 1][ai] = av0.y;
        Aw[aw + 2][ai] = av0.z; Aw[aw + 3][ai] = av0.w;
        Aw[aw + 4][ai] = av1.x; Aw[aw + 5][ai] = av1.y;
        Aw[aw + 6][ai] = av1.z; Aw[aw + 7][ai] = av1.w;
        if (BT) {
            Bw[aw + 0][ai] = bv0.x; Bw[aw + 1][ai] = bv0.y;
            Bw[aw + 2][ai] = bv0.z; Bw[aw + 3][ai] = bv0.w;
            Bw[aw + 4][ai] = bv1.x; Bw[aw + 5][ai] = bv1.y;
            Bw[aw + 6][ai] = bv1.z; Bw[aw + 7][ai] = bv1.w;
        } else {
            *reinterpret_cast<float4*>(&Bw[br][bc]) = bv0;
            *reinterpret_cast<float4*>(&Bw[br + 8][bc]) = bv1;
        }
    }
    __syncthreads();

    int cur = 0;
    for (int k0 = 0; k0 < K; k0 += 16) {
        const bool more = (k0 + 16) < K;
        if (more) {
            const int kn = k0 + 16;
            av0 = *reinterpret_cast<const float4*>(&A[(size_t)ai * lda + kn + aw]);
            av1 = *reinterpret_cast<const float4*>(&A[(size_t)ai * lda + kn + aw + 4]);
            if (BT) {
                bv0 = *reinterpret_cast<const float4*>(&B[(size_t)ai * ldb + kn + aw]);
                bv1 = *reinterpret_cast<const float4*>(&B[(size_t)ai * ldb + kn + aw + 4]);
            } else {
                bv0 = *reinterpret_cast<const float4*>(&B[(size_t)(kn + br) * ldb + bc]);
                bv1 = *reinterpret_cast<const float4*>(&B[(size_t)(kn + 8 + br) * ldb + bc]);
            }
        }
        const float (*Ac)[132] = As[cur];
        const float (*Bc)[132] = Bs[cur];
        #pragma unroll
        for (int kk = 0; kk < 16; kk++) {
            float4 a0 = *reinterpret_cast<const float4*>(&Ac[kk][ty * 8]);
            float4 a1 = *reinterpret_cast<const float4*>(&Ac[kk][ty * 8 + 4]);
            float4 b0 = *reinterpret_cast<const float4*>(&Bc[kk][tx * 8]);
            float4 b1 = *reinterpret_cast<const float4*>(&Bc[kk][tx * 8 + 4]);
            float a[8] = {a0.x, a0.y, a0.z, a0.w, a1.x, a1.y, a1.z, a1.w};
            float b[8] = {b0.x, b0.y, b0.z, b0.w, b1.x, b1.y, b1.z, b1.w};
            #pragma unroll
            for (int i = 0; i < 8; i++)
                #pragma unroll
                for (int j = 0; j < 8; j++) acc[i][j] += a[i] * b[j];
        }
        if (more) {
            float (*Aw)[132] = As[cur ^ 1];
            float (*Bw)[132] = Bs[cur ^ 1];
            Aw[aw + 0][ai] = av0.x; Aw[aw + 1][ai] = av0.y;
            Aw[aw + 2][ai] = av0.z; Aw[aw + 3][ai] = av0.w;
            Aw[aw + 4][ai] = av1.x; Aw[aw + 5][ai] = av1.y;
            Aw[aw + 6][ai] = av1.z; Aw[aw + 7][ai] = av1.w;
            if (BT) {
                Bw[aw + 0][ai] = bv0.x; Bw[aw + 1][ai] = bv0.y;
                Bw[aw + 2][ai] = bv0.z; Bw[aw + 3][ai] = bv0.w;
                Bw[aw + 4][ai] = bv1.x; Bw[aw + 5][ai] = bv1.y;
                Bw[aw + 6][ai] = bv1.z; Bw[aw + 7][ai] = bv1.w;
            } else {
                *reinterpret_cast<float4*>(&Bw[br][bc]) = bv0;
                *reinterpret_cast<float4*>(&Bw[br + 8][bc]) = bv1;
            }
            __syncthreads();
            cur ^= 1;
        }
    }
}

// ---------------- general tiled GEMM (SYRK / residual) ---------------------
// MODE 0: C -= AB   MODE 1: C = AB   MODE 2: C = D - c1*AB - c2*E
template <int BT, int MODE>
__global__ __launch_bounds__(256, 2)
void gemm_kernel(const float* __restrict__ A, int lda,
                 const float* __restrict__ B, int ldb,
                 float* __restrict__ C, int ldc, int K, int triSkip,
                 const float* __restrict__ D,
                 const float* __restrict__ E) {
    const int bx = blockIdx.x, by = blockIdx.y;
    if (triSkip && by < bx) return;
    const int r0 = by * 128, c0 = bx * 128;

    float acc[8][8];
    #pragma unroll
    for (int i = 0; i < 8; i++)
        #pragma unroll
        for (int j = 0; j < 8; j++) acc[i][j] = 0.0f;

    const float* At = A + (size_t)r0 * lda;
    const float* Bt = BT ? (B + (size_t)c0 * ldb) : (B + c0);
    gemm_db<BT>(At, lda, Bt, ldb, acc, K);

    const int tx = threadIdx.x & 15, ty = threadIdx.x >> 4;
    float c1 = 0.0f, c2 = 0.0f;
    if (MODE == 2) { c1 = g_scal[0]; c2 = g_scal[1]; }
    #pragma unroll
    for (int i = 0; i < 8; i++) {
        size_t base = (size_t)(r0 + ty * 8 + i) * ldc + c0 + tx * 8;
        #pragma unroll
        for (int j = 0; j < 8; j++) {
            if (MODE == 0) C[base + j] -= acc[i][j];
            else if (MODE == 1) C[base + j] = acc[i][j];
            else C[base + j] = D[base + j] - c1 * acc[i][j] - c2 * E[base + j];
        }
    }
}

// ---------------- fused diag (Cholesky+inverse) + panel TRSM ---------------
// grid (1 + nt) blocks, 256 threads, dynamic smem 128*129 floats.
// Block 0: factor diag block k, invert, publish g_Linv, raise flag.
// Blocks >=1: spin on flag, then L21 row = A21 * Linv_k^T (in place).
// All blocks co-resident (grid <= 32 <= #SMs) -> spin is deadlock-free.
__global__ void fused_dp_kernel(int k) {
    extern __shared__ float s[];  // [128][129]
    const int tid = threadIdx.x;  // 256

    if (blockIdx.x == 0) {
        float* blk = &g_M[(size_t)(k * NB) * N_DIM + (size_t)k * NB];
        for (int idx = tid; idx < NB * NB; idx += 256) {
            int r = idx >> 7, c = idx & 127;
            s[r * 129 + c] = blk[(size_t)r * N_DIM + c];
        }
        __syncthreads();

        // Cholesky sweep: column scaled by rsqrt(diag); diag fixed up at end.
        const int ui = tid >> 1, ulane = tid & 1;
        for (int j = 0; j < NB; j++) {
            float rs = rsqrtf(s[j * 129 + j]);
            if (tid < NB && tid > j) s[tid * 129 + j] *= rs;
            __syncthreads();
            if (ui > j) {
                float lij = s[ui * 129 + j];
                for (int c = j + 1 + ulane; c <= ui; c += 2)
                    s[ui * 129 + c] -= lij * s[c * 129 + j];
            }
            __syncthreads();
        }
        if (tid < NB) s[tid * 129 + tid] = sqrtf(s[tid * 129 + tid]);
        __syncthreads();

        for (int idx = tid; idx < NB * NB; idx += 256) {
            int r = idx >> 7, c = idx & 127;
            blk[(size_t)r * N_DIM + c] = s[r * 129 + c];
        }

        // in-place triangular inverse: 2 lanes per column, row sweep
        const int c2 = tid >> 1, lane = tid & 1;
        for (int j = 0; j < NB; j++) {
            float sum = 0.0f;
            for (int p = c2 + lane; p < j; p += 2)
                sum += s[j * 129 + p] * s[p * 129 + c2];
            sum += __shfl_down_sync(0xffffffffu, sum, 1, 2);
            float val = (((j == c2) ? 1.0f : 0.0f) - sum) / s[j * 129 + j];
            __syncthreads();
            if (c2 <= j && lane == 0) s[j * 129 + c2] = val;
            __syncthreads();
        }
        float* go = &g_Linv[(size_t)k * NB * NB];
        for (int idx = tid; idx < NB * NB; idx += 256) {
            int r = idx >> 7, c = idx & 127;
            go[idx] = (r >= c) ? s[r * 129 + c] : 0.0f;
        }
        __syncthreads();
        if (tid == 0) {
            __threadfence();
            atomicExch(&g_flag[k], 1);
        }
    } else {
        if (tid == 0) {
            while (atomicAdd(&g_flag[k], 0) == 0) {}
        }
        __syncthreads();
        __threadfence();
        const int t = k + blockIdx.x;
        float* A21row = g_M + (size_t)t * NB * N_DIM + (size_t)k * NB;
        float acc[8][8];
        #pragma unroll
        for (int i = 0; i < 8; i++)
            #pragma unroll
            for (int j = 0; j < 8; j++) acc[i][j] = 0.0f;
        gemm_db<1>(A21row, N_DIM, g_Linv + (size_t)k * NB * NB, NB, acc, NB);
        const int tx = tid & 15, ty = tid >> 4;
        #pragma unroll
        for (int i = 0; i < 8; i++) {
            size_t base = (size_t)(ty * 8 + i) * N_DIM + tx * 8;
            #pragma unroll
            for (int j = 0; j < 8; j++) A21row[base + j] = acc[i][j];
        }
    }
}

// ---------------- F/G precompute INTO g_M ----------------------------------
// lower (i,j), i>j:  G_{i,j}=Linv_i*L_{i,j} -> upper (j,i);
//                    F_{i,j}=L_{i,j}*Linv_j -> in place (i,j).
__global__ __launch_bounds__(256, 2) void fg_kernel() {
    const int j = blockIdx.x, i = blockIdx.y;
    if (i <= j) return;
    float* Lij = g_M + (size_t)i * NB * N_DIM + (size_t)j * NB;
    const int tx = threadIdx.x & 15, ty = threadIdx.x >> 4;

    float acc[8][8];
    #pragma unroll
    for (int a = 0; a < 8; a++)
        #pragma unroll
        for (int b = 0; b < 8; b++) acc[a][b] = 0.0f;
    gemm_db<0>(g_Linv + (size_t)i * NB * NB, NB, Lij, N_DIM, acc, NB);
    float* Gdst = g_M + (size_t)j * NB * N_DIM + (size_t)i * NB;
    #pragma unroll
    for (int a = 0; a < 8; a++) {
        size_t base = (size_t)(ty * 8 + a) * N_DIM + tx * 8;
        #pragma unroll
        for (int b = 0; b < 8; b++) Gdst[base + b] = acc[a][b];
    }
    __syncthreads();

    #pragma unroll
    for (int a = 0; a < 8; a++)
        #pragma unroll
        for (int b = 0; b < 8; b++) acc[a][b] = 0.0f;
    gemm_db<0>(Lij, N_DIM, g_Linv + (size_t)j * NB * NB, NB, acc, NB);
    #pragma unroll
    for (int a = 0; a < 8; a++) {
        size_t base = (size_t)(ty * 8 + a) * N_DIM + tx * 8;
        #pragma unroll
        for (int b = 0; b < 8; b++) Lij[base + b] = acc[a][b];
    }
}

// ---------------- fused forward-solve step ---------------------------------
// grid (NPAN-k, 4). bx==0: Xout_k = Xwork_k * Linv_k^T.
// bx>0: Xwork_{k+bx} -= Xwork_k * F_{k+bx,k}^T.
__global__ __launch_bounds__(256, 2)
void fwd_step_kernel(const float* __restrict__ Xwork, float* __restrict__ Xout,
                     int k) {
    const int bx = blockIdx.x, by = blockIdx.y;
    const float* A = Xwork + (size_t)(by * NB) * N_DIM + (size_t)k * NB;
    const float* B; int ldb; float* C; int sub;
    if (bx == 0) {
        B = g_Linv + (size_t)k * NB * NB; ldb = NB;
        C = Xout + (size_t)(by * NB) * N_DIM + (size_t)k * NB; sub = 0;
    } else {
        int t = k + bx;
        B = g_M + (size_t)t * NB * N_DIM + (size_t)k * NB; ldb = N_DIM;  // F
        C = const_cast<float*>(Xwork) + (size_t)(by * NB) * N_DIM + (size_t)t * NB;
        sub = 1;
    }
    float acc[8][8];
    #pragma unroll
    for (int i = 0; i < 8; i++)
        #pragma unroll
        for (int j = 0; j < 8; j++) acc[i][j] = 0.0f;
    gemm_db<1>(A, N_DIM, B, ldb, acc, NB);
    const int tx = threadIdx.x & 15, ty = threadIdx.x >> 4;
    #pragma unroll
    for (int i = 0; i < 8; i++) {
        size_t base = (size_t)(ty * 8 + i) * N_DIM + tx * 8;
        #pragma unroll
        for (int j = 0; j < 8; j++) {
            if (sub) C[base + j] -= acc[i][j];
            else C[base + j] = acc[i][j];
        }
    }
}

// ---------------- fused backward-solve step --------------------------------
// grid (k+1, 4). bx==k: Zout_k (=|+=) V_k * Linv_k.
// bx<k: V_bx -= V_k * G_{k,bx} (stored at upper block (bx,k)).
__global__ __launch_bounds__(256, 2)
void bwd_step_kernel(const float* __restrict__ V, float* __restrict__ Zout,
                     int k, int accum) {
    const int bx = blockIdx.x, by = blockIdx.y;
    const float* A = V + (size_t)(by * NB) * N_DIM + (size_t)k * NB;
    const float* B; int ldb; float* C; int mode;
    if (bx == k) {
        B = g_Linv + (size_t)k * NB * NB; ldb = NB;
        C = Zout + (size_t)(by * NB) * N_DIM + (size_t)k * NB; mode = 0;
    } else {
        B = g_M + (size_t)bx * NB * N_DIM + (size_t)k * NB; ldb = N_DIM;  // G
        C = const_cast<float*>(V) + (size_t)(by * NB) * N_DIM + (size_t)bx * NB;
        mode = 1;
    }
    float acc[8][8];
    #pragma unroll
    for (int i = 0; i < 8; i++)
        #pragma unroll
        for (int j = 0; j < 8; j++) acc[i][j] = 0.0f;
    gemm_db<0>(A, N_DIM, B, ldb, acc, NB);
    const int tx = threadIdx.x & 15, ty = threadIdx.x >> 4;
    #pragma unroll
    for (int i = 0; i < 8; i++) {
        size_t base = (size_t)(ty * 8 + i) * N_DIM + tx * 8;
        #pragma unroll
        for (int j = 0; j < 8; j++) {
            if (mode) C[base + j] -= acc[i][j];
            else if (accum) C[base + j] += acc[i][j];
            else C[base + j] = acc[i][j];
        }
    }
}

// ---------------- finish: denom_i = a * <z_i, k_i>; out = z / denom --------
__global__ void finish_kernel(const float* __restrict__ Kb,
                              const float* __restrict__ a_p,
                              float* __restrict__ out) {
    const int row = blockIdx.x;
    const float* z = &g_X3[(size_t)row * N_DIM];
    const float* kk = &Kb[(size_t)row * N_DIM];
    __shared__ float red[8];
    __shared__ float dsh;
    int tid = threadIdx.x;  // 256
    float s = 0.0f;
    for (int j = tid; j < N_DIM; j += 256) s += z[j] * kk[j];
    #pragma unroll
    for (int o = 16; o > 0; o >>= 1) s += __shfl_down_sync(0xffffffffu, s, o);
    if ((tid & 31) == 0) red[tid >> 5] = s;
    __syncthreads();
    if (tid == 0) {
        float t = 0.0f;
        #pragma unroll
        for (int w = 0; w < 8; w++) t += red[w];
        dsh = 1.0f / (a_p[0] * t);
    }
    __syncthreads();
    float d = dsh;
    for (int j = tid; j < N_DIM; j += 256)
        out[(size_t)row * N_DIM + j] = z[j] * d;
}

// ---------------- host orchestration --------------------------------------
extern "C" void kernel_launch(void* const* d_in, const int* in_sizes, int n_in,
                              void* d_out, int out_size) {
    // Bind inputs BY SIZE (robust to metadata ordering).
    const float* Kb = nullptr;
    const float* Phi = nullptr;
    const float* v1024a = nullptr;
    const float* v1024b = nullptr;
    const float* a_p = nullptr;
    const float* gam = nullptr;
    for (int i = 0; i < n_in; i++) {
        int sz = in_sizes[i];
        const float* p = (const float*)d_in[i];
        if (sz == N_DIM * N_DIM) Phi = p;
        else if (sz == B_DIM * N_DIM) Kb = p;
        else if (sz == 1024) { if (!v1024a) v1024a = p; else v1024b = p; }
        else if (sz == 1) { if (!a_p) a_p = p; else gam = p; }
    }
    (void)out_size;

    const int dynSmem = 128 * 129 * (int)sizeof(float);  // ~66 KB
    cudaFuncSetAttribute(fused_dp_kernel,
                         cudaFuncAttributeMaxDynamicSharedMemorySize, dynSmem);

    float *pM, *pX1, *pX2, *pX3;
    cudaGetSymbolAddress((void**)&pM, g_M);
    cudaGetSymbolAddress((void**)&pX1, g_X1);
    cudaGetSymbolAddress((void**)&pX2, g_X2);
    cudaGetSymbolAddress((void**)&pX3, g_X3);

    scalars_kernel<<<1, 1024>>>(v1024a, v1024b, gam);
    build_M_kernel<<<4096, 256>>>(Phi);

    // blocked right-looking Cholesky: fused diag+panel, then SYRK
    for (int k = 0; k < NPAN; k++) {
        int nt = NPAN - 1 - k;
        fused_dp_kernel<<<1 + nt, 256, dynSmem>>>(k);
        if (nt > 0) {
            float* A21 = pM + (size_t)(k + 1) * NB * N_DIM + (size_t)k * NB;
            float* C22 = pM + (size_t)(k + 1) * NB * N_DIM + (size_t)(k + 1) * NB;
            dim3 gs(nt, nt);  // SYRK (lower tiles only)
            gemm_kernel<1, 0><<<gs, 256>>>(A21, N_DIM, A21, N_DIM, C22, N_DIM,
                                           NB, 1, nullptr, nullptr);
        }
    }

    // F (lower, in place) and G (upper) panels: one wide launch
    fg_kernel<<<dim3(NPAN, NPAN), 256>>>();

    // ---- solve 1: Z = K * L^{-T} * L^{-1} ----
    size_t n4 = (size_t)B_DIM * N_DIM / 4;
    copy_kernel<<<1024, 256>>>(pX1, Kb, n4);
    for (int k = 0; k < NPAN; k++)
        fwd_step_kernel<<<dim3(NPAN - k, B_DIM / NB), 256>>>(pX1, pX2, k);
    for (int k = NPAN - 1; k >= 0; k--)
        bwd_step_kernel<<<dim3(k + 1, B_DIM / NB), 256>>>(pX2, pX3, k, 0);

    // ---- iterative refinement: R = K - c1*Z*Phi - c2*Z; solve; Z += E ----
    gemm_kernel<0, 2><<<dim3(N_DIM / NB, B_DIM / NB), 256>>>(
        pX3, N_DIM, Phi, N_DIM, pX1, N_DIM, N_DIM, 0, Kb, pX3);
    for (int k = 0; k < NPAN; k++)
        fwd_step_kernel<<<dim3(NPAN - k, B_DIM / NB), 256>>>(pX1, pX2, k);
    for (int k = NPAN - 1; k >= 0; k--)
        bwd_step_kernel<<<dim3(k + 1, B_DIM / NB), 256>>>(pX2, pX3, k, 1);

    finish_kernel<<<B_DIM, 256>>>(Kb, a_p, (float*)d_out);
}

// round 10
// speedup vs baseline: 1.1751x; 1.1751x over previous
#include <cuda_runtime.h>
#include <math.h>
#include <stdint.h>

#define N_DIM 4096
#define B_DIM 512
#define NB 128
#define NPAN (N_DIM / NB)

// ---------------- device scratch ------------------------------------------
__device__ float g_M[(size_t)N_DIM * N_DIM];   // 64 MB: M -> L -> F(lower)/G(upper)
__device__ float g_Linv[NPAN * NB * NB];       // 2 MB: diag-block inverses
__device__ float g_X1[(size_t)B_DIM * N_DIM];  // 8 MB workspaces
__device__ float g_X2[(size_t)B_DIM * N_DIM];
__device__ float g_X3[(size_t)B_DIM * N_DIM];
__device__ float g_scal[4];                    // c1, c2

// ---------------- scalars: c1=(||imp||^2+||exc||^2)/B, c2=gamma/B ----------
__global__ void scalars_kernel(const float* __restrict__ imp,
                               const float* __restrict__ exc,
                               const float* __restrict__ gamma_p) {
    __shared__ float red[32];
    int tid = threadIdx.x;  // 1024
    float v = imp[tid] * imp[tid] + exc[tid] * exc[tid];
    #pragma unroll
    for (int o = 16; o > 0; o >>= 1) v += __shfl_down_sync(0xffffffffu, v, o);
    if ((tid & 31) == 0) red[tid >> 5] = v;
    __syncthreads();
    if (tid < 32) {
        float s = red[tid];
        #pragma unroll
        for (int o = 16; o > 0; o >>= 1) s += __shfl_down_sync(0xffffffffu, s, o);
        if (tid == 0) {
            g_scal[0] = s / (float)B_DIM;
            g_scal[1] = gamma_p[0] / (float)B_DIM;
        }
    }
}

// ---------------- build M = c1*Phi + c2*I ---------------------------------
__global__ void build_M_kernel(const float* __restrict__ Phi) {
    const float c1 = g_scal[0], c2 = g_scal[1];
    size_t total = (size_t)N_DIM * N_DIM;
    for (size_t i = (size_t)blockIdx.x * blockDim.x + threadIdx.x; i < total;
         i += (size_t)gridDim.x * blockDim.x) {
        float v = c1 * Phi[i];
        if ((i >> 12) == (i & 4095)) v += c2;
        g_M[i] = v;
    }
}

__global__ void copy_kernel(float* __restrict__ dst, const float* __restrict__ src,
                            size_t n4) {
    for (size_t i = (size_t)blockIdx.x * blockDim.x + threadIdx.x; i < n4;
         i += (size_t)gridDim.x * blockDim.x) {
        reinterpret_cast<float4*>(dst)[i] = reinterpret_cast<const float4*>(src)[i];
    }
}

// ---------------- 128x128 diag block: Cholesky + in-place inverse ----------
// 1 block, 1024 threads, dynamic smem = 128*129 floats (~66 KB)  [R7-proven]
__global__ void chol_diag_kernel(int k) {
    extern __shared__ float s[];    // [128][129]
    const int tid = threadIdx.x;
    float* blk = &g_M[(size_t)(k * NB) * N_DIM + (size_t)k * NB];

    for (int idx = tid; idx < NB * NB; idx += 1024) {
        int r = idx >> 7, c = idx & 127;
        s[r * 129 + c] = blk[(size_t)r * N_DIM + c];
    }
    __syncthreads();

    // Cholesky: column j scaled by rsqrt(diag); diag fixed up at end.
    const int ui = tid >> 3, ulane = tid & 7;
    for (int j = 0; j < NB; j++) {
        float rs = rsqrtf(s[j * 129 + j]);
        if (tid < NB && tid > j) s[tid * 129 + j] *= rs;
        __syncthreads();
        if (ui > j) {
            float lij = s[ui * 129 + j];
            for (int c = j + 1 + ulane; c <= ui; c += 8)
                s[ui * 129 + c] -= lij * s[c * 129 + j];
        }
        __syncthreads();
    }
    if (tid < NB) s[tid * 129 + tid] = sqrtf(s[tid * 129 + tid]);
    __syncthreads();

    for (int idx = tid; idx < NB * NB; idx += 1024) {
        int r = idx >> 7, c = idx & 127;
        blk[(size_t)r * N_DIM + c] = s[r * 129 + c];
    }

    // in-place inverse: 8 lanes per column, row sweep.
    const int c8 = tid >> 3, lane = tid & 7;
    for (int j = 0; j < NB; j++) {
        float sum = 0.0f;
        for (int p = c8 + lane; p < j; p += 8)
            sum += s[j * 129 + p] * s[p * 129 + c8];
        sum += __shfl_down_sync(0xffffffffu, sum, 4, 8);
        sum += __shfl_down_sync(0xffffffffu, sum, 2, 8);
        sum += __shfl_down_sync(0xffffffffu, sum, 1, 8);
        float val = (((j == c8) ? 1.0f : 0.0f) - sum) / s[j * 129 + j];
        __syncthreads();
        if (c8 <= j && lane == 0) s[j * 129 + c8] = val;
        __syncthreads();
    }
    float* go = &g_Linv[(size_t)k * NB * NB];
    for (int idx = tid; idx < NB * NB; idx += 1024) {
        int r = idx >> 7, c = idx & 127;
        go[idx] = (r >= c) ? s[r * 129 + c] : 0.0f;
    }
}

// ---------------- double-buffered 128-wide GEMM microkernel ----------------
// A pre-offset to tile row start; B pre-offset to tile col start.
// BT=1: acc += A(128xK) * B(128xK)^T ; BT=0: acc += A(128xK) * B(Kx128).
// K multiple of 16.  256 threads.  One barrier per 16-K step.  [R8-proven]
template <int BT>
__device__ __forceinline__ void gemm_db(const float* __restrict__ A, int lda,
                                        const float* __restrict__ B, int ldb,
                                        float acc[8][8], int K) {
    __shared__ float As[2][16][132];
    __shared__ float Bs[2][16][132];
    const int tid = threadIdx.x;
    const int ai = tid >> 1;
    const int aw = (tid & 1) << 3;
    const int br = tid >> 5;
    const int bc = (tid & 31) << 2;
    const int ty = tid >> 4, tx = tid & 15;

    float4 av0, av1, bv0, bv1;
    av0 = *reinterpret_cast<const float4*>(&A[(size_t)ai * lda + aw]);
    av1 = *reinterpret_cast<const float4*>(&A[(size_t)ai * lda + aw + 4]);
    if (BT) {
        bv0 = *reinterpret_cast<const float4*>(&B[(size_t)ai * ldb + aw]);
        bv1 = *reinterpret_cast<const float4*>(&B[(size_t)ai * ldb + aw + 4]);
    } else {
        bv0 = *reinterpret_cast<const float4*>(&B[(size_t)br * ldb + bc]);
        bv1 = *reinterpret_cast<const float4*>(&B[(size_t)(br + 8) * ldb + bc]);
    }
    {
        float (*Aw)[132] = As[0];
        float (*Bw)[132] = Bs[0];
        Aw[aw + 0][ai] = av0.x; Aw[aw + 1][ai] = av0.y;
        Aw[aw + 2][ai] = av0.z; Aw[aw + 3][ai] = av0.w;
        Aw[aw + 4][ai] = av1.x; Aw[aw + 5][ai] = av1.y;
        Aw[aw + 6][ai] = av1.z; Aw[aw + 7][ai] = av1.w;
        if (BT) {
            Bw[aw + 0][ai] = bv0.x; Bw[aw + 1][ai] = bv0.y;
            Bw[aw + 2][ai] = bv0.z; Bw[aw + 3][ai] = bv0.w;
            Bw[aw + 4][ai] = bv1.x; Bw[aw + 5][ai] = bv1.y;
            Bw[aw + 6][ai] = bv1.z; Bw[aw + 7][ai] = bv1.w;
        } else {
            *reinterpret_cast<float4*>(&Bw[br][bc]) = bv0;
            *reinterpret_cast<float4*>(&Bw[br + 8][bc]) = bv1;
        }
    }
    __syncthreads();

    int cur = 0;
    for (int k0 = 0; k0 < K; k0 += 16) {
        const bool more = (k0 + 16) < K;
        if (more) {
            const int kn = k0 + 16;
            av0 = *reinterpret_cast<const float4*>(&A[(size_t)ai * lda + kn + aw]);
            av1 = *reinterpret_cast<const float4*>(&A[(size_t)ai * lda + kn + aw + 4]);
            if (BT) {
                bv0 = *reinterpret_cast<const float4*>(&B[(size_t)ai * ldb + kn + aw]);
                bv1 = *reinterpret_cast<const float4*>(&B[(size_t)ai * ldb + kn + aw + 4]);
            } else {
                bv0 = *reinterpret_cast<const float4*>(&B[(size_t)(kn + br) * ldb + bc]);
                bv1 = *reinterpret_cast<const float4*>(&B[(size_t)(kn + 8 + br) * ldb + bc]);
            }
        }
        const float (*Ac)[132] = As[cur];
        const float (*Bc)[132] = Bs[cur];
        #pragma unroll
        for (int kk = 0; kk < 16; kk++) {
            float4 a0 = *reinterpret_cast<const float4*>(&Ac[kk][ty * 8]);
            float4 a1 = *reinterpret_cast<const float4*>(&Ac[kk][ty * 8 + 4]);
            float4 b0 = *reinterpret_cast<const float4*>(&Bc[kk][tx * 8]);
            float4 b1 = *reinterpret_cast<const float4*>(&Bc[kk][tx * 8 + 4]);
            float a[8] = {a0.x, a0.y, a0.z, a0.w, a1.x, a1.y, a1.z, a1.w};
            float b[8] = {b0.x, b0.y, b0.z, b0.w, b1.x, b1.y, b1.z, b1.w};
            #pragma unroll
            for (int i = 0; i < 8; i++)
                #pragma unroll
                for (int j = 0; j < 8; j++) acc[i][j] += a[i] * b[j];
        }
        if (more) {
            float (*Aw)[132] = As[cur ^ 1];
            float (*Bw)[132] = Bs[cur ^ 1];
            Aw[aw + 0][ai] = av0.x; Aw[aw + 1][ai] = av0.y;
            Aw[aw + 2][ai] = av0.z; Aw[aw + 3][ai] = av0.w;
            Aw[aw + 4][ai] = av1.x; Aw[aw + 5][ai] = av1.y;
            Aw[aw + 6][ai] = av1.z; Aw[aw + 7][ai] = av1.w;
            if (BT) {
                Bw[aw + 0][ai] = bv0.x; Bw[aw + 1][ai] = bv0.y;
                Bw[aw + 2][ai] = bv0.z; Bw[aw + 3][ai] = bv0.w;
                Bw[aw + 4][ai] = bv1.x; Bw[aw + 5][ai] = bv1.y;
                Bw[aw + 6][ai] = bv1.z; Bw[aw + 7][ai] = bv1.w;
            } else {
                *reinterpret_cast<float4*>(&Bw[br][bc]) = bv0;
                *reinterpret_cast<float4*>(&Bw[br + 8][bc]) = bv1;
            }
            __syncthreads();
            cur ^= 1;
        }
    }
}

// ---------------- general tiled GEMM (panel TRSM / SYRK / residual) --------
// MODE 0: C -= AB   MODE 1: C = AB   MODE 2: C = D - c1*AB - c2*E
template <int BT, int MODE>
__global__ __launch_bounds__(256, 2)
void gemm_kernel(const float* __restrict__ A, int lda,
                 const float* __restrict__ B, int ldb,
                 float* __restrict__ C, int ldc, int K, int triSkip,
                 const float* __restrict__ D,
                 const float* __restrict__ E) {
    const int bx = blockIdx.x, by = blockIdx.y;
    if (triSkip && by < bx) return;
    const int r0 = by * 128, c0 = bx * 128;

    float acc[8][8];
    #pragma unroll
    for (int i = 0; i < 8; i++)
        #pragma unroll
        for (int j = 0; j < 8; j++) acc[i][j] = 0.0f;

    const float* At = A + (size_t)r0 * lda;
    const float* Bt = BT ? (B + (size_t)c0 * ldb) : (B + c0);
    gemm_db<BT>(At, lda, Bt, ldb, acc, K);

    const int tx = threadIdx.x & 15, ty = threadIdx.x >> 4;
    float c1 = 0.0f, c2 = 0.0f;
    if (MODE == 2) { c1 = g_scal[0]; c2 = g_scal[1]; }
    #pragma unroll
    for (int i = 0; i < 8; i++) {
        size_t base = (size_t)(r0 + ty * 8 + i) * ldc + c0 + tx * 8;
        #pragma unroll
        for (int j = 0; j < 8; j++) {
            if (MODE == 0) C[base + j] -= acc[i][j];
            else if (MODE == 1) C[base + j] = acc[i][j];
            else C[base + j] = D[base + j] - c1 * acc[i][j] - c2 * E[base + j];
        }
    }
}

// ---------------- F/G precompute INTO g_M ----------------------------------
// lower (i,j), i>j:  G_{i,j}=Linv_i*L_{i,j} -> upper (j,i);
//                    F_{i,j}=L_{i,j}*Linv_j -> in place (i,j).
__global__ __launch_bounds__(256, 2) void fg_kernel() {
    const int j = blockIdx.x, i = blockIdx.y;
    if (i <= j) return;
    float* Lij = g_M + (size_t)i * NB * N_DIM + (size_t)j * NB;
    const int tx = threadIdx.x & 15, ty = threadIdx.x >> 4;

    float acc[8][8];
    #pragma unroll
    for (int a = 0; a < 8; a++)
        #pragma unroll
        for (int b = 0; b < 8; b++) acc[a][b] = 0.0f;
    gemm_db<0>(g_Linv + (size_t)i * NB * NB, NB, Lij, N_DIM, acc, NB);
    float* Gdst = g_M + (size_t)j * NB * N_DIM + (size_t)i * NB;
    #pragma unroll
    for (int a = 0; a < 8; a++) {
        size_t base = (size_t)(ty * 8 + a) * N_DIM + tx * 8;
        #pragma unroll
        for (int b = 0; b < 8; b++) Gdst[base + b] = acc[a][b];
    }
    __syncthreads();

    #pragma unroll
    for (int a = 0; a < 8; a++)
        #pragma unroll
        for (int b = 0; b < 8; b++) acc[a][b] = 0.0f;
    gemm_db<0>(Lij, N_DIM, g_Linv + (size_t)j * NB * NB, NB, acc, NB);
    #pragma unroll
    for (int a = 0; a < 8; a++) {
        size_t base = (size_t)(ty * 8 + a) * N_DIM + tx * 8;
        #pragma unroll
        for (int b = 0; b < 8; b++) Lij[base + b] = acc[a][b];
    }
}

// ---------------- fused forward-solve step ---------------------------------
// grid (NPAN-k, 4). bx==0: Xout_k = Xwork_k * Linv_k^T.
// bx>0: Xwork_{k+bx} -= Xwork_k * F_{k+bx,k}^T.  Both read OLD Xwork_k.
__global__ __launch_bounds__(256, 2)
void fwd_step_kernel(const float* __restrict__ Xwork, float* __restrict__ Xout,
                     int k) {
    const int bx = blockIdx.x, by = blockIdx.y;
    const float* A = Xwork + (size_t)(by * NB) * N_DIM + (size_t)k * NB;
    const float* B; int ldb; float* C; int sub;
    if (bx == 0) {
        B = g_Linv + (size_t)k * NB * NB; ldb = NB;
        C = Xout + (size_t)(by * NB) * N_DIM + (size_t)k * NB; sub = 0;
    } else {
        int t = k + bx;
        B = g_M + (size_t)t * NB * N_DIM + (size_t)k * NB; ldb = N_DIM;  // F
        C = const_cast<float*>(Xwork) + (size_t)(by * NB) * N_DIM + (size_t)t * NB;
        sub = 1;
    }
    float acc[8][8];
    #pragma unroll
    for (int i = 0; i < 8; i++)
        #pragma unroll
        for (int j = 0; j < 8; j++) acc[i][j] = 0.0f;
    gemm_db<1>(A, N_DIM, B, ldb, acc, NB);
    const int tx = threadIdx.x & 15, ty = threadIdx.x >> 4;
    #pragma unroll
    for (int i = 0; i < 8; i++) {
        size_t base = (size_t)(ty * 8 + i) * N_DIM + tx * 8;
        #pragma unroll
        for (int j = 0; j < 8; j++) {
            if (sub) C[base + j] -= acc[i][j];
            else C[base + j] = acc[i][j];
        }
    }
}

// ---------------- fused backward-solve step --------------------------------
// grid (k+1, 4). bx==k: Zout_k (=|+=) V_k * Linv_k.
// bx<k: V_bx -= V_k * G_{k,bx} (stored at upper block (bx,k)).
__global__ __launch_bounds__(256, 2)
void bwd_step_kernel(const float* __restrict__ V, float* __restrict__ Zout,
                     int k, int accum) {
    const int bx = blockIdx.x, by = blockIdx.y;
    const float* A = V + (size_t)(by * NB) * N_DIM + (size_t)k * NB;
    const float* B; int ldb; float* C; int mode;
    if (bx == k) {
        B = g_Linv + (size_t)k * NB * NB; ldb = NB;
        C = Zout + (size_t)(by * NB) * N_DIM + (size_t)k * NB; mode = 0;
    } else {
        B = g_M + (size_t)bx * NB * N_DIM + (size_t)k * NB; ldb = N_DIM;  // G
        C = const_cast<float*>(V) + (size_t)(by * NB) * N_DIM + (size_t)bx * NB;
        mode = 1;
    }
    float acc[8][8];
    #pragma unroll
    for (int i = 0; i < 8; i++)
        #pragma unroll
        for (int j = 0; j < 8; j++) acc[i][j] = 0.0f;
    gemm_db<0>(A, N_DIM, B, ldb, acc, NB);
    const int tx = threadIdx.x & 15, ty = threadIdx.x >> 4;
    #pragma unroll
    for (int i = 0; i < 8; i++) {
        size_t base = (size_t)(ty * 8 + i) * N_DIM + tx * 8;
        #pragma unroll
        for (int j = 0; j < 8; j++) {
            if (mode) C[base + j] -= acc[i][j];
            else if (accum) C[base + j] += acc[i][j];
            else C[base + j] = acc[i][j];
        }
    }
}

// ---------------- finish: denom_i = a * <z_i, k_i>; out = z / denom --------
__global__ void finish_kernel(const float* __restrict__ Kb,
                              const float* __restrict__ a_p,
                              float* __restrict__ out) {
    const int row = blockIdx.x;
    const float* z = &g_X3[(size_t)row * N_DIM];
    const float* kk = &Kb[(size_t)row * N_DIM];
    __shared__ float red[8];
    __shared__ float dsh;
    int tid = threadIdx.x;  // 256
    float s = 0.0f;
    for (int j = tid; j < N_DIM; j += 256) s += z[j] * kk[j];
    #pragma unroll
    for (int o = 16; o > 0; o >>= 1) s += __shfl_down_sync(0xffffffffu, s, o);
    if ((tid & 31) == 0) red[tid >> 5] = s;
    __syncthreads();
    if (tid == 0) {
        float t = 0.0f;
        #pragma unroll
        for (int w = 0; w < 8; w++) t += red[w];
        dsh = 1.0f / (a_p[0] * t);
    }
    __syncthreads();
    float d = dsh;
    for (int j = tid; j < N_DIM; j += 256)
        out[(size_t)row * N_DIM + j] = z[j] * d;
}

// ---------------- host orchestration --------------------------------------
extern "C" void kernel_launch(void* const* d_in, const int* in_sizes, int n_in,
                              void* d_out, int out_size) {
    // Bind inputs BY SIZE (robust to metadata ordering).
    const float* Kb = nullptr;
    const float* Phi = nullptr;
    const float* v1024a = nullptr;
    const float* v1024b = nullptr;
    const float* a_p = nullptr;
    const float* gam = nullptr;
    for (int i = 0; i < n_in; i++) {
        int sz = in_sizes[i];
        const float* p = (const float*)d_in[i];
        if (sz == N_DIM * N_DIM) Phi = p;
        else if (sz == B_DIM * N_DIM) Kb = p;
        else if (sz == 1024) { if (!v1024a) v1024a = p; else v1024b = p; }
        else if (sz == 1) { if (!a_p) a_p = p; else gam = p; }
    }
    (void)out_size;

    const int dynSmem = 128 * 129 * (int)sizeof(float);  // ~66 KB
    cudaFuncSetAttribute(chol_diag_kernel,
                         cudaFuncAttributeMaxDynamicSharedMemorySize, dynSmem);

    float *pM, *pLinv, *pX1, *pX2, *pX3;
    cudaGetSymbolAddress((void**)&pM, g_M);
    cudaGetSymbolAddress((void**)&pLinv, g_Linv);
    cudaGetSymbolAddress((void**)&pX1, g_X1);
    cudaGetSymbolAddress((void**)&pX2, g_X2);
    cudaGetSymbolAddress((void**)&pX3, g_X3);

    scalars_kernel<<<1, 1024>>>(v1024a, v1024b, gam);
    build_M_kernel<<<4096, 256>>>(Phi);

    // blocked right-looking Cholesky (R7 structure, R8 microkernel)
    for (int k = 0; k < NPAN; k++) {
        chol_diag_kernel<<<1, 1024, dynSmem>>>(k);
        int nt = NPAN - 1 - k;
        if (nt > 0) {
            float* A21 = pM + (size_t)(k + 1) * NB * N_DIM + (size_t)k * NB;
            dim3 gp(1, nt);   // panel: L21 = A21 * Linv_k^T (in place)
            gemm_kernel<1, 1><<<gp, 256>>>(A21, N_DIM,
                                           pLinv + (size_t)k * NB * NB, NB, A21,
                                           N_DIM, NB, 0, nullptr, nullptr);
            float* C22 = pM + (size_t)(k + 1) * NB * N_DIM + (size_t)(k + 1) * NB;
            dim3 gs(nt, nt);  // SYRK (lower tiles only)
            gemm_kernel<1, 0><<<gs, 256>>>(A21, N_DIM, A21, N_DIM, C22, N_DIM,
                                           NB, 1, nullptr, nullptr);
        }
    }

    // F (lower, in place) and G (upper) panels: one wide launch
    fg_kernel<<<dim3(NPAN, NPAN), 256>>>();

    // ---- solve 1: Z = K * L^{-T} * L^{-1} ----
    size_t n4 = (size_t)B_DIM * N_DIM / 4;
    copy_kernel<<<1024, 256>>>(pX1, Kb, n4);
    for (int k = 0; k < NPAN; k++)
        fwd_step_kernel<<<dim3(NPAN - k, B_DIM / NB), 256>>>(pX1, pX2, k);
    for (int k = NPAN - 1; k >= 0; k--)
        bwd_step_kernel<<<dim3(k + 1, B_DIM / NB), 256>>>(pX2, pX3, k, 0);

    // ---- iterative refinement: R = K - c1*Z*Phi - c2*Z; solve; Z += E ----
    gemm_kernel<0, 2><<<dim3(N_DIM / NB, B_DIM / NB), 256>>>(
        pX3, N_DIM, Phi, N_DIM, pX1, N_DIM, N_DIM, 0, Kb, pX3);
    for (int k = 0; k < NPAN; k++)
        fwd_step_kernel<<<dim3(NPAN - k, B_DIM / NB), 256>>>(pX1, pX2, k);
    for (int k = NPAN - 1; k >= 0; k--)
        bwd_step_kernel<<<dim3(k + 1, B_DIM / NB), 256>>>(pX2, pX3, k, 1);

    finish_kernel<<<B_DIM, 256>>>(Kb, a_p, (float*)d_out);
}

// round 13
// speedup vs baseline: 1.2027x; 1.0235x over previous
#include <cuda_runtime.h>
#include <math.h>
#include <stdint.h>

#define N_DIM 4096
#define B_DIM 512
#define NB 128
#define NPAN (N_DIM / NB)
#define PERS_BLOCKS 128
#define SMEM_GEMM (4 * 16 * 132 * (int)sizeof(float))  // 33792 B

// ---------------- device scratch ------------------------------------------
__device__ float g_M[(size_t)N_DIM * N_DIM];   // 64 MB: M -> L -> F(lower)/G(upper)
__device__ float g_Linv[NPAN * NB * NB];       // 2 MB: diag-block inverses
__device__ float g_X1[(size_t)B_DIM * N_DIM];  // 8 MB workspaces
__device__ float g_X2[(size_t)B_DIM * N_DIM];
__device__ float g_X3[(size_t)B_DIM * N_DIM];
__device__ float g_scal[4];                    // c1, c2
__device__ unsigned int g_bar[192];            // grid-barrier counters

// ---------------- scalars + barrier reset ----------------------------------
__global__ void scalars_kernel(const float* __restrict__ imp,
                               const float* __restrict__ exc,
                               const float* __restrict__ gamma_p) {
    __shared__ float red[32];
    int tid = threadIdx.x;  // 1024
    if (tid < 192) g_bar[tid] = 0u;
    float v = imp[tid] * imp[tid] + exc[tid] * exc[tid];
    #pragma unroll
    for (int o = 16; o > 0; o >>= 1) v += __shfl_down_sync(0xffffffffu, v, o);
    if ((tid & 31) == 0) red[tid >> 5] = v;
    __syncthreads();
    if (tid < 32) {
        float s = red[tid];
        #pragma unroll
        for (int o = 16; o > 0; o >>= 1) s += __shfl_down_sync(0xffffffffu, s, o);
        if (tid == 0) {
            g_scal[0] = s / (float)B_DIM;
            g_scal[1] = gamma_p[0] / (float)B_DIM;
        }
    }
}

// ---------------- build M = c1*Phi + c2*I ---------------------------------
__global__ void build_M_kernel(const float* __restrict__ Phi) {
    const float c1 = g_scal[0], c2 = g_scal[1];
    size_t total = (size_t)N_DIM * N_DIM;
    for (size_t i = (size_t)blockIdx.x * blockDim.x + threadIdx.x; i < total;
         i += (size_t)gridDim.x * blockDim.x) {
        float v = c1 * Phi[i];
        if ((i >> 12) == (i & 4095)) v += c2;
        g_M[i] = v;
    }
}

// ---------------- 128x128 diag block: Cholesky + in-place inverse ----------
// 1 block, 1024 threads, dynamic smem = 128*129 floats (~66 KB)  [R7-proven]
__global__ void chol_diag_kernel(int k) {
    extern __shared__ float s[];    // [128][129]
    const int tid = threadIdx.x;
    float* blk = &g_M[(size_t)(k * NB) * N_DIM + (size_t)k * NB];

    for (int idx = tid; idx < NB * NB; idx += 1024) {
        int r = idx >> 7, c = idx & 127;
        s[r * 129 + c] = blk[(size_t)r * N_DIM + c];
    }
    __syncthreads();

    const int ui = tid >> 3, ulane = tid & 7;
    for (int j = 0; j < NB; j++) {
        float rs = rsqrtf(s[j * 129 + j]);
        if (tid < NB && tid > j) s[tid * 129 + j] *= rs;
        __syncthreads();
        if (ui > j) {
            float lij = s[ui * 129 + j];
            for (int c = j + 1 + ulane; c <= ui; c += 8)
                s[ui * 129 + c] -= lij * s[c * 129 + j];
        }
        __syncthreads();
    }
    if (tid < NB) s[tid * 129 + tid] = sqrtf(s[tid * 129 + tid]);
    __syncthreads();

    for (int idx = tid; idx < NB * NB; idx += 1024) {
        int r = idx >> 7, c = idx & 127;
        blk[(size_t)r * N_DIM + c] = s[r * 129 + c];
    }

    const int c8 = tid >> 3, lane = tid & 7;
    for (int j = 0; j < NB; j++) {
        float sum = 0.0f;
        for (int p = c8 + lane; p < j; p += 8)
            sum += s[j * 129 + p] * s[p * 129 + c8];
        sum += __shfl_down_sync(0xffffffffu, sum, 4, 8);
        sum += __shfl_down_sync(0xffffffffu, sum, 2, 8);
        sum += __shfl_down_sync(0xffffffffu, sum, 1, 8);
        float val = (((j == c8) ? 1.0f : 0.0f) - sum) / s[j * 129 + j];
        __syncthreads();
        if (c8 <= j && lane == 0) s[j * 129 + c8] = val;
        __syncthreads();
    }
    float* go = &g_Linv[(size_t)k * NB * NB];
    for (int idx = tid; idx < NB * NB; idx += 1024) {
        int r = idx >> 7, c = idx & 127;
        go[idx] = (r >= c) ? s[r * 129 + c] : 0.0f;
    }
}

// ---------------- double-buffered 128-wide GEMM microkernel ----------------
// Dynamic-smem version: caller passes a 33792-byte buffer (reused across calls).
// BT=1: acc += A(128xK) * B(128xK)^T ; BT=0: acc += A(128xK) * B(Kx128).
template <int BT>
__device__ __forceinline__ void gemm_db(float* sm, const float* __restrict__ A,
                                        int lda, const float* __restrict__ B,
                                        int ldb, float acc[8][8], int K) {
    float (*As)[16][132] = reinterpret_cast<float (*)[16][132]>(sm);
    float (*Bs)[16][132] = reinterpret_cast<float (*)[16][132]>(sm + 2 * 16 * 132);
    const int tid = threadIdx.x;
    const int ai = tid >> 1;
    const int aw = (tid & 1) << 3;
    const int br = tid >> 5;
    const int bc = (tid & 31) << 2;
    const int ty = tid >> 4, tx = tid & 15;

    float4 av0, av1, bv0, bv1;
    av0 = *reinterpret_cast<const float4*>(&A[(size_t)ai * lda + aw]);
    av1 = *reinterpret_cast<const float4*>(&A[(size_t)ai * lda + aw + 4]);
    if (BT) {
        bv0 = *reinterpret_cast<const float4*>(&B[(size_t)ai * ldb + aw]);
        bv1 = *reinterpret_cast<const float4*>(&B[(size_t)ai * ldb + aw + 4]);
    } else {
        bv0 = *reinterpret_cast<const float4*>(&B[(size_t)br * ldb + bc]);
        bv1 = *reinterpret_cast<const float4*>(&B[(size_t)(br + 8) * ldb + bc]);
    }
    {
        float (*Aw)[132] = As[0];
        float (*Bw)[132] = Bs[0];
        Aw[aw + 0][ai] = av0.x; Aw[aw + 1][ai] = av0.y;
        Aw[aw + 2][ai] = av0.z; Aw[aw + 3][ai] = av0.w;
        Aw[aw + 4][ai] = av1.x; Aw[aw + 5][ai] = av1.y;
        Aw[aw + 6][ai] = av1.z; Aw[aw + 7][ai] = av1.w;
        if (BT) {
            Bw[aw + 0][ai] = bv0.x; Bw[aw + 1][ai] = bv0.y;
            Bw[aw + 2][ai] = bv0.z; Bw[aw + 3][ai] = bv0.w;
            Bw[aw + 4][ai] = bv1.x; Bw[aw + 5][ai] = bv1.y;
            Bw[aw + 6][ai] = bv1.z; Bw[aw + 7][ai] = bv1.w;
        } else {
            *reinterpret_cast<float4*>(&Bw[br][bc]) = bv0;
            *reinterpret_cast<float4*>(&Bw[br + 8][bc]) = bv1;
        }
    }
    __syncthreads();

    int cur = 0;
    for (int k0 = 0; k0 < K; k0 += 16) {
        const bool more = (k0 + 16) < K;
        if (more) {
            const int kn = k0 + 16;
            av0 = *reinterpret_cast<const float4*>(&A[(size_t)ai * lda + kn + aw]);
            av1 = *reinterpret_cast<const float4*>(&A[(size_t)ai * lda + kn + aw + 4]);
            if (BT) {
                bv0 = *reinterpret_cast<const float4*>(&B[(size_t)ai * ldb + kn + aw]);
                bv1 = *reinterpret_cast<const float4*>(&B[(size_t)ai * ldb + kn + aw + 4]);
            } else {
                bv0 = *reinterpret_cast<const float4*>(&B[(size_t)(kn + br) * ldb + bc]);
                bv1 = *reinterpret_cast<const float4*>(&B[(size_t)(kn + 8 + br) * ldb + bc]);
            }
        }
        const float (*Ac)[132] = As[cur];
        const float (*Bc)[132] = Bs[cur];
        #pragma unroll
        for (int kk = 0; kk < 16; kk++) {
            float4 a0 = *reinterpret_cast<const float4*>(&Ac[kk][ty * 8]);
            float4 a1 = *reinterpret_cast<const float4*>(&Ac[kk][ty * 8 + 4]);
            float4 b0 = *reinterpret_cast<const float4*>(&Bc[kk][tx * 8]);
            float4 b1 = *reinterpret_cast<const float4*>(&Bc[kk][tx * 8 + 4]);
            float a[8] = {a0.x, a0.y, a0.z, a0.w, a1.x, a1.y, a1.z, a1.w};
            float b[8] = {b0.x, b0.y, b0.z, b0.w, b1.x, b1.y, b1.z, b1.w};
            #pragma unroll
            for (int i = 0; i < 8; i++)
                #pragma unroll
                for (int j = 0; j < 8; j++) acc[i][j] += a[i] * b[j];
        }
        if (more) {
            float (*Aw)[132] = As[cur ^ 1];
            float (*Bw)[132] = Bs[cur ^ 1];
            Aw[aw + 0][ai] = av0.x; Aw[aw + 1][ai] = av0.y;
            Aw[aw + 2][ai] = av0.z; Aw[aw + 3][ai] = av0.w;
            Aw[aw + 4][ai] = av1.x; Aw[aw + 5][ai] = av1.y;
            Aw[aw + 6][ai] = av1.z; Aw[aw + 7][ai] = av1.w;
            if (BT) {
                Bw[aw + 0][ai] = bv0.x; Bw[aw + 1][ai] = bv0.y;
                Bw[aw + 2][ai] = bv0.z; Bw[aw + 3][ai] = bv0.w;
                Bw[aw + 4][ai] = bv1.x; Bw[aw + 5][ai] = bv1.y;
                Bw[aw + 6][ai] = bv1.z; Bw[aw + 7][ai] = bv1.w;
            } else {
                *reinterpret_cast<float4*>(&Bw[br][bc]) = bv0;
                *reinterpret_cast<float4*>(&Bw[br + 8][bc]) = bv1;
            }
            __syncthreads();
            cur ^= 1;
        }
    }
}

// ---------------- general tiled GEMM (panel TRSM / SYRK) -------------------
// MODE 0: C -= AB   MODE 1: C = AB
template <int BT, int MODE>
__global__ __launch_bounds__(256, 2)
void gemm_kernel(const float* __restrict__ A, int lda,
                 const float* __restrict__ B, int ldb,
                 float* __restrict__ C, int ldc, int K, int triSkip) {
    extern __shared__ float sm[];
    const int bx = blockIdx.x, by = blockIdx.y;
    if (triSkip && by < bx) return;
    const int r0 = by * 128, c0 = bx * 128;

    float acc[8][8];
    #pragma unroll
    for (int i = 0; i < 8; i++)
        #pragma unroll
        for (int j = 0; j < 8; j++) acc[i][j] = 0.0f;

    const float* At = A + (size_t)r0 * lda;
    const float* Bt = BT ? (B + (size_t)c0 * ldb) : (B + c0);
    gemm_db<BT>(sm, At, lda, Bt, ldb, acc, K);

    const int tx = threadIdx.x & 15, ty = threadIdx.x >> 4;
    #pragma unroll
    for (int i = 0; i < 8; i++) {
        size_t base = (size_t)(r0 + ty * 8 + i) * ldc + c0 + tx * 8;
        #pragma unroll
        for (int j = 0; j < 8; j++) {
            if (MODE == 0) C[base + j] -= acc[i][j];
            else C[base + j] = acc[i][j];
        }
    }
}

// ---------------- F/G precompute INTO g_M ----------------------------------
// lower (i,j), i>j:  G_{i,j}=Linv_i*L_{i,j} -> upper (j,i);
//                    F_{i,j}=L_{i,j}*Linv_j -> in place (i,j).
__global__ __launch_bounds__(256, 2) void fg_kernel() {
    extern __shared__ float sm[];
    const int j = blockIdx.x, i = blockIdx.y;
    if (i <= j) return;
    float* Lij = g_M + (size_t)i * NB * N_DIM + (size_t)j * NB;
    const int tx = threadIdx.x & 15, ty = threadIdx.x >> 4;

    float acc[8][8];
    #pragma unroll
    for (int a = 0; a < 8; a++)
        #pragma unroll
        for (int b = 0; b < 8; b++) acc[a][b] = 0.0f;
    gemm_db<0>(sm, g_Linv + (size_t)i * NB * NB, NB, Lij, N_DIM, acc, NB);
    float* Gdst = g_M + (size_t)j * NB * N_DIM + (size_t)i * NB;
    #pragma unroll
    for (int a = 0; a < 8; a++) {
        size_t base = (size_t)(ty * 8 + a) * N_DIM + tx * 8;
        #pragma unroll
        for (int b = 0; b < 8; b++) Gdst[base + b] = acc[a][b];
    }
    __syncthreads();

    #pragma unroll
    for (int a = 0; a < 8; a++)
        #pragma unroll
        for (int b = 0; b < 8; b++) acc[a][b] = 0.0f;
    gemm_db<0>(sm, Lij, N_DIM, g_Linv + (size_t)j * NB * NB, NB, acc, NB);
    #pragma unroll
    for (int a = 0; a < 8; a++) {
        size_t base = (size_t)(ty * 8 + a) * N_DIM + tx * 8;
        #pragma unroll
        for (int b = 0; b < 8; b++) Lij[base + b] = acc[a][b];
    }
}

// ---------------- grid-wide barrier (co-resident grid only) ----------------
// Safe: PERS_BLOCKS=128 blocks x 256thr x 33.8KB smem all fit in wave 1 on
// 148 SMs, so every block is resident before any spin begins.
__device__ __forceinline__ void grid_bar(int idx) {
    __syncthreads();
    if (threadIdx.x == 0) {
        __threadfence();
        atomicAdd(&g_bar[idx], 1u);
        while (((volatile unsigned int*)g_bar)[idx] < gridDim.x) {
            __nanosleep(64);
        }
        __threadfence();
    }
    __syncthreads();
}

// ---------------- persistent solve kernel ----------------------------------
// ONE launch for: X1=K; 2x{forward 32 steps; backward 32 steps}; residual;
// finish. 128 blocks (co-resident on 148 SMs), 256 threads, 33792 B smem.
__global__ __launch_bounds__(256)
void solve_all_kernel(const float* __restrict__ Kb, const float* __restrict__ Phi,
                      const float* __restrict__ a_p, float* __restrict__ out) {
    extern __shared__ float sm[];
    const int bid = blockIdx.x;   // 128
    const int tid = threadIdx.x;  // 256
    const int tx = tid & 15, ty = tid >> 4;
    int barIdx = 0;

    // step 0: X1 = K
    {
        size_t n4 = (size_t)B_DIM * N_DIM / 4;
        const float4* src = reinterpret_cast<const float4*>(Kb);
        float4* dst = reinterpret_cast<float4*>(g_X1);
        for (size_t i = (size_t)bid * 256 + tid; i < n4; i += (size_t)PERS_BLOCKS * 256)
            dst[i] = src[i];
    }
    grid_bar(barIdx++);

    for (int pass = 0; pass < 2; pass++) {
        // ---- forward: X1 (work) -> X2 (out) ----
        for (int k = 0; k < NPAN; k++) {
            int ntile = 4 * (NPAN - k);
            if (bid < ntile) {
                int bx = bid >> 2, by = bid & 3;
                const float* A = g_X1 + (size_t)(by * NB) * N_DIM + (size_t)k * NB;
                float acc[8][8];
                #pragma unroll
                for (int i = 0; i < 8; i++)
                    #pragma unroll
                    for (int j = 0; j < 8; j++) acc[i][j] = 0.0f;
                if (bx == 0) {
                    gemm_db<1>(sm, A, N_DIM, g_Linv + (size_t)k * NB * NB, NB, acc, NB);
                    float* C = g_X2 + (size_t)(by * NB) * N_DIM + (size_t)k * NB;
                    #pragma unroll
                    for (int i = 0; i < 8; i++) {
                        size_t base = (size_t)(ty * 8 + i) * N_DIM + tx * 8;
                        #pragma unroll
                        for (int j = 0; j < 8; j++) C[base + j] = acc[i][j];
                    }
                } else {
                    int t = k + bx;
                    gemm_db<1>(sm, A, N_DIM,
                               g_M + (size_t)t * NB * N_DIM + (size_t)k * NB, N_DIM,
                               acc, NB);
                    float* C = g_X1 + (size_t)(by * NB) * N_DIM + (size_t)t * NB;
                    #pragma unroll
                    for (int i = 0; i < 8; i++) {
                        size_t base = (size_t)(ty * 8 + i) * N_DIM + tx * 8;
                        #pragma unroll
                        for (int j = 0; j < 8; j++) C[base + j] -= acc[i][j];
                    }
                }
            }
            grid_bar(barIdx++);
        }
        // ---- backward: X2 (work) -> X3 (out; pass1 accumulates) ----
        for (int k = NPAN - 1; k >= 0; k--) {
            int ntile = 4 * (k + 1);
            if (bid < ntile) {
                int bx = bid >> 2, by = bid & 3;
                const float* A = g_X2 + (size_t)(by * NB) * N_DIM + (size_t)k * NB;
                float acc[8][8];
                #pragma unroll
                for (int i = 0; i < 8; i++)
                    #pragma unroll
                    for (int j = 0; j < 8; j++) acc[i][j] = 0.0f;
                if (bx == k) {
                    gemm_db<0>(sm, A, N_DIM, g_Linv + (size_t)k * NB * NB, NB, acc, NB);
                    float* C = g_X3 + (size_t)(by * NB) * N_DIM + (size_t)k * NB;
                    #pragma unroll
                    for (int i = 0; i < 8; i++) {
                        size_t base = (size_t)(ty * 8 + i) * N_DIM + tx * 8;
                        #pragma unroll
                        for (int j = 0; j < 8; j++) {
                            if (pass) C[base + j] += acc[i][j];
                            else C[base + j] = acc[i][j];
                        }
                    }
                } else {
                    gemm_db<0>(sm, A, N_DIM,
                               g_M + (size_t)bx * NB * N_DIM + (size_t)k * NB, N_DIM,
                               acc, NB);
                    float* C = g_X2 + (size_t)(by * NB) * N_DIM + (size_t)bx * NB;
                    #pragma unroll
                    for (int i = 0; i < 8; i++) {
                        size_t base = (size_t)(ty * 8 + i) * N_DIM + tx * 8;
                        #pragma unroll
                        for (int j = 0; j < 8; j++) C[base + j] -= acc[i][j];
                    }
                }
            }
            grid_bar(barIdx++);
        }
        if (pass == 0) {
            // ---- residual: X1 = Kb - c1*X3*Phi - c2*X3  (128 tiles) ----
            int bx = bid >> 2, by = bid & 3;  // bx 0..31, by 0..3
            int r0 = by * 128, c0 = bx * 128;
            float acc[8][8];
            #pragma unroll
            for (int i = 0; i < 8; i++)
                #pragma unroll
                for (int j = 0; j < 8; j++) acc[i][j] = 0.0f;
            gemm_db<0>(sm, g_X3 + (size_t)r0 * N_DIM, N_DIM, Phi + c0, N_DIM,
                       acc, N_DIM);
            const float c1 = g_scal[0], c2 = g_scal[1];
            #pragma unroll
            for (int i = 0; i < 8; i++) {
                size_t base = (size_t)(r0 + ty * 8 + i) * N_DIM + c0 + tx * 8;
                #pragma unroll
                for (int j = 0; j < 8; j++)
                    g_X1[base + j] = Kb[base + j] - c1 * acc[i][j] - c2 * g_X3[base + j];
            }
            grid_bar(barIdx++);
        }
    }

    // ---- finish: out = X3 row / (a * <X3 row, K row>), 4 rows per block ----
    {
        float* red = sm;         // 8 warp partials
        float* dshp = sm + 8;    // broadcast slot
        const float a_val = a_p[0];
        for (int rr = 0; rr < 4; rr++) {
            int row = bid * 4 + rr;
            const float* z = &g_X3[(size_t)row * N_DIM];
            const float* kk = &Kb[(size_t)row * N_DIM];
            float s = 0.0f;
            for (int j = tid; j < N_DIM; j += 256) s += z[j] * kk[j];
            #pragma unroll
            for (int o = 16; o > 0; o >>= 1)
                s += __shfl_down_sync(0xffffffffu, s, o);
            if ((tid & 31) == 0) red[tid >> 5] = s;
            __syncthreads();
            if (tid == 0) {
                float t = 0.0f;
                #pragma unroll
                for (int w = 0; w < 8; w++) t += red[w];
                dshp[0] = 1.0f / (a_val * t);
            }
            __syncthreads();
            float d = dshp[0];
            for (int j = tid; j < N_DIM; j += 256)
                out[(size_t)row * N_DIM + j] = z[j] * d;
            __syncthreads();
        }
    }
}

// ---------------- host orchestration --------------------------------------
extern "C" void kernel_launch(void* const* d_in, const int* in_sizes, int n_in,
                              void* d_out, int out_size) {
    // Bind inputs BY SIZE (robust to metadata ordering).
    const float* Kb = nullptr;
    const float* Phi = nullptr;
    const float* v1024a = nullptr;
    const float* v1024b = nullptr;
    const float* a_p = nullptr;
    const float* gam = nullptr;
    for (int i = 0; i < n_in; i++) {
        int sz = in_sizes[i];
        const float* p = (const float*)d_in[i];
        if (sz == N_DIM * N_DIM) Phi = p;
        else if (sz == B_DIM * N_DIM) Kb = p;
        else if (sz == 1024) { if (!v1024a) v1024a = p; else v1024b = p; }
        else if (sz == 1) { if (!a_p) a_p = p; else gam = p; }
    }
    (void)out_size;

    const int dynSmemDiag = 128 * 129 * (int)sizeof(float);  // ~66 KB
    cudaFuncSetAttribute(chol_diag_kernel,
                         cudaFuncAttributeMaxDynamicSharedMemorySize, dynSmemDiag);

    float* pM;
    float* pLinv;
    cudaGetSymbolAddress((void**)&pM, g_M);
    cudaGetSymbolAddress((void**)&pLinv, g_Linv);

    scalars_kernel<<<1, 1024>>>(v1024a, v1024b, gam);
    build_M_kernel<<<4096, 256>>>(Phi);

    // blocked right-looking Cholesky (R7 structure, dynamic-smem microkernel)
    for (int k = 0; k < NPAN; k++) {
        chol_diag_kernel<<<1, 1024, dynSmemDiag>>>(k);
        int nt = NPAN - 1 - k;
        if (nt > 0) {
            float* A21 = pM + (size_t)(k + 1) * NB * N_DIM + (size_t)k * NB;
            dim3 gp(1, nt);   // panel: L21 = A21 * Linv_k^T (in place)
            gemm_kernel<1, 1><<<gp, 256, SMEM_GEMM>>>(
                A21, N_DIM, pLinv + (size_t)k * NB * NB, NB, A21, N_DIM, NB, 0);
            float* C22 = pM + (size_t)(k + 1) * NB * N_DIM + (size_t)(k + 1) * NB;
            dim3 gs(nt, nt);  // SYRK (lower tiles only)
            gemm_kernel<1, 0><<<gs, 256, SMEM_GEMM>>>(
                A21, N_DIM, A21, N_DIM, C22, N_DIM, NB, 1);
        }
    }

    // F (lower, in place) and G (upper) panels: one wide launch
    fg_kernel<<<dim3(NPAN, NPAN), 256, SMEM_GEMM>>>();

    // everything else: ONE persistent launch (solve1, IR residual+solve2, finish)
    solve_all_kernel<<<PERS_BLOCKS, 256, SMEM_GEMM>>>(Kb, Phi, a_p, (float*)d_out);
}

// round 14
// speedup vs baseline: 1.2530x; 1.0418x over previous
#include <cuda_runtime.h>
#include <math.h>
#include <stdint.h>

#define N_DIM 4096
#define B_DIM 512
#define NB 128
#define NPAN (N_DIM / NB)
#define PERS_BLOCKS 128
#define SMEM_GEMM (4 * 16 * 132 * (int)sizeof(float))  // 33792 B

// ---------------- device scratch ------------------------------------------
__device__ float g_M[(size_t)N_DIM * N_DIM];   // 64 MB: M -> L -> F(lower)/G(upper)
__device__ float g_Linv[NPAN * NB * NB];       // 2 MB: diag-block inverses
__device__ float g_X1[(size_t)B_DIM * N_DIM];  // 8 MB workspaces
__device__ float g_X2[(size_t)B_DIM * N_DIM];
__device__ float g_X3[(size_t)B_DIM * N_DIM];
__device__ float g_scal[4];                    // c1, c2
__device__ unsigned int g_bar[192];            // grid-barrier counters

// ---------------- scalars + barrier reset ----------------------------------
__global__ void scalars_kernel(const float* __restrict__ imp,
                               const float* __restrict__ exc,
                               const float* __restrict__ gamma_p) {
    __shared__ float red[32];
    int tid = threadIdx.x;  // 1024
    if (tid < 192) g_bar[tid] = 0u;
    float v = imp[tid] * imp[tid] + exc[tid] * exc[tid];
    #pragma unroll
    for (int o = 16; o > 0; o >>= 1) v += __shfl_down_sync(0xffffffffu, v, o);
    if ((tid & 31) == 0) red[tid >> 5] = v;
    __syncthreads();
    if (tid < 32) {
        float s = red[tid];
        #pragma unroll
        for (int o = 16; o > 0; o >>= 1) s += __shfl_down_sync(0xffffffffu, s, o);
        if (tid == 0) {
            g_scal[0] = s / (float)B_DIM;
            g_scal[1] = gamma_p[0] / (float)B_DIM;
        }
    }
}

// ---------------- build M = c1*Phi + c2*I ---------------------------------
__global__ void build_M_kernel(const float* __restrict__ Phi) {
    const float c1 = g_scal[0], c2 = g_scal[1];
    size_t total = (size_t)N_DIM * N_DIM;
    for (size_t i = (size_t)blockIdx.x * blockDim.x + threadIdx.x; i < total;
         i += (size_t)gridDim.x * blockDim.x) {
        float v = c1 * Phi[i];
        if ((i >> 12) == (i & 4095)) v += c2;
        g_M[i] = v;
    }
}

// ---------------- 128x128 diag block: panel-blocked Cholesky + inverse -----
// 1 block, 1024 threads. Dynamic smem: s (L) + xs (X) = 2*128*129 floats.
// ~26 block barriers total (vs 512 in the column-wise version).
__global__ void chol_diag_kernel(int k) {
    extern __shared__ float sh[];
    float* s = sh;                 // [128][129] L workspace
    float* xs = sh + 128 * 129;    // [128][129] X = L^{-1} workspace
    __shared__ float Wt[32 * 33];  // temp for 32x32 block GEMMs
    const int tid = threadIdx.x;   // 1024
    const int warp = tid >> 5, lane = tid & 31;
    float* blk = &g_M[(size_t)(k * NB) * N_DIM + (size_t)k * NB];

    for (int idx = tid; idx < NB * NB; idx += 1024) {
        int r = idx >> 7, c = idx & 127;
        s[r * 129 + c] = blk[(size_t)r * N_DIM + c];
    }
    __syncthreads();

    // ---- blocked Cholesky: 4 panels of 32 columns ----
    for (int p0 = 0; p0 < NB; p0 += 32) {
        // A1: warp 0 factors the 32x32 corner (lane = row within corner)
        if (warp == 0) {
            const int R = p0 + lane;
            for (int j = 0; j < 32; j++) {
                if (lane == j) s[R * 129 + p0 + j] = sqrtf(s[R * 129 + p0 + j]);
                __syncwarp();
                float dinv = 1.0f / s[(p0 + j) * 129 + p0 + j];
                if (lane > j) s[R * 129 + p0 + j] *= dinv;
                __syncwarp();
                if (lane > j) {
                    float lij = s[R * 129 + p0 + j];
                    for (int c = j + 1; c <= lane; c++)
                        s[R * 129 + p0 + c] -= lij * s[(p0 + c) * 129 + p0 + j];
                }
                __syncwarp();
            }
        }
        __syncthreads();
        // A2: panel TRSM below corner, one thread per row (rows independent)
        const int nrows = NB - (p0 + 32);
        if (tid < nrows) {
            const int R = p0 + 32 + tid;
            for (int j = 0; j < 32; j++) {
                float sum = s[R * 129 + p0 + j];
                for (int c = 0; c < j; c++)
                    sum -= s[R * 129 + p0 + c] * s[(p0 + j) * 129 + p0 + c];
                s[R * 129 + p0 + j] = sum / s[(p0 + j) * 129 + p0 + j];
            }
        }
        __syncthreads();
        // A3: rank-32 trailing update (full rectangle; upper junk never read)
        if (nrows > 0) {
            int tot = nrows * nrows;
            for (int t = tid; t < tot; t += 1024) {
                int i = t / nrows, j = t % nrows;
                int R = p0 + 32 + i, C = p0 + 32 + j;
                float sum = 0.0f;
                #pragma unroll 8
                for (int jj = 0; jj < 32; jj++)
                    sum += s[R * 129 + p0 + jj] * s[C * 129 + p0 + jj];
                s[R * 129 + C] -= sum;
            }
        }
        __syncthreads();
    }

    // write L back (upper junk never read before fg overwrites)
    for (int idx = tid; idx < NB * NB; idx += 1024) {
        int r = idx >> 7, c = idx & 127;
        blk[(size_t)r * N_DIM + c] = s[r * 129 + c];
    }

    // ---- C1: 4 corner inverses in parallel, warp w inverts block (w,w) ----
    // lane owns column c: only reads/writes its own X column -> no syncs.
    if (warp < 4) {
        const int b0 = warp * 32;
        const int c = lane;
        for (int j = 0; j < 32; j++) {
            float val = 0.0f;
            if (j >= c) {
                float sum = (j == c) ? 1.0f : 0.0f;
                for (int p = c; p < j; p++)
                    sum -= s[(b0 + j) * 129 + b0 + p] * xs[(b0 + p) * 129 + b0 + c];
                val = sum / s[(b0 + j) * 129 + b0 + j];
            }
            xs[(b0 + j) * 129 + b0 + c] = val;
        }
    }
    __syncthreads();

    // ---- C2: off-diagonal blocks by block forward substitution ----
    // X_pq = -X_pp * (sum_{r=q}^{p-1} L_pr * X_rq), processed by diagonal d.
    {
        const int i = tid >> 5, j = tid & 31;  // 32x32 = 1024 threads exactly
        for (int d = 1; d < 4; d++) {
            for (int q = 0; q + d < 4; q++) {
                const int p = q + d;
                float sum = 0.0f;
                for (int r = q; r < p; r++) {
                    float ss = 0.0f;
                    #pragma unroll 8
                    for (int kk = 0; kk < 32; kk++)
                        ss += s[(p * 32 + i) * 129 + r * 32 + kk] *
                              xs[(r * 32 + kk) * 129 + q * 32 + j];
                    sum += ss;
                }
                Wt[i * 33 + j] = sum;
                __syncthreads();
                float acc = 0.0f;
                #pragma unroll 8
                for (int kk = 0; kk < 32; kk++)
                    acc += xs[(p * 32 + i) * 129 + p * 32 + kk] * Wt[kk * 33 + j];
                __syncthreads();
                xs[(p * 32 + i) * 129 + q * 32 + j] = -acc;
                __syncthreads();
            }
        }
    }

    // ---- C3: write X to g_Linv (zeros above diagonal) ----
    float* go = &g_Linv[(size_t)k * NB * NB];
    for (int idx = tid; idx < NB * NB; idx += 1024) {
        int r = idx >> 7, c = idx & 127;
        go[idx] = (r >= c) ? xs[r * 129 + c] : 0.0f;
    }
}

// ---------------- double-buffered 128-wide GEMM microkernel ----------------
// Dynamic-smem version: caller passes a 33792-byte buffer (reused across calls).
// BT=1: acc += A(128xK) * B(128xK)^T ; BT=0: acc += A(128xK) * B(Kx128).
template <int BT>
__device__ __forceinline__ void gemm_db(float* sm, const float* __restrict__ A,
                                        int lda, const float* __restrict__ B,
                                        int ldb, float acc[8][8], int K) {
    float (*As)[16][132] = reinterpret_cast<float (*)[16][132]>(sm);
    float (*Bs)[16][132] = reinterpret_cast<float (*)[16][132]>(sm + 2 * 16 * 132);
    const int tid = threadIdx.x;
    const int ai = tid >> 1;
    const int aw = (tid & 1) << 3;
    const int br = tid >> 5;
    const int bc = (tid & 31) << 2;
    const int ty = tid >> 4, tx = tid & 15;

    float4 av0, av1, bv0, bv1;
    av0 = *reinterpret_cast<const float4*>(&A[(size_t)ai * lda + aw]);
    av1 = *reinterpret_cast<const float4*>(&A[(size_t)ai * lda + aw + 4]);
    if (BT) {
        bv0 = *reinterpret_cast<const float4*>(&B[(size_t)ai * ldb + aw]);
        bv1 = *reinterpret_cast<const float4*>(&B[(size_t)ai * ldb + aw + 4]);
    } else {
        bv0 = *reinterpret_cast<const float4*>(&B[(size_t)br * ldb + bc]);
        bv1 = *reinterpret_cast<const float4*>(&B[(size_t)(br + 8) * ldb + bc]);
    }
    {
        float (*Aw)[132] = As[0];
        float (*Bw)[132] = Bs[0];
        Aw[aw + 0][ai] = av0.x; Aw[aw + 1][ai] = av0.y;
        Aw[aw + 2][ai] = av0.z; Aw[aw + 3][ai] = av0.w;
        Aw[aw + 4][ai] = av1.x; Aw[aw + 5][ai] = av1.y;
        Aw[aw + 6][ai] = av1.z; Aw[aw + 7][ai] = av1.w;
        if (BT) {
            Bw[aw + 0][ai] = bv0.x; Bw[aw + 1][ai] = bv0.y;
            Bw[aw + 2][ai] = bv0.z; Bw[aw + 3][ai] = bv0.w;
            Bw[aw + 4][ai] = bv1.x; Bw[aw + 5][ai] = bv1.y;
            Bw[aw + 6][ai] = bv1.z; Bw[aw + 7][ai] = bv1.w;
        } else {
            *reinterpret_cast<float4*>(&Bw[br][bc]) = bv0;
            *reinterpret_cast<float4*>(&Bw[br + 8][bc]) = bv1;
        }
    }
    __syncthreads();

    int cur = 0;
    for (int k0 = 0; k0 < K; k0 += 16) {
        const bool more = (k0 + 16) < K;
        if (more) {
            const int kn = k0 + 16;
            av0 = *reinterpret_cast<const float4*>(&A[(size_t)ai * lda + kn + aw]);
            av1 = *reinterpret_cast<const float4*>(&A[(size_t)ai * lda + kn + aw + 4]);
            if (BT) {
                bv0 = *reinterpret_cast<const float4*>(&B[(size_t)ai * ldb + kn + aw]);
                bv1 = *reinterpret_cast<const float4*>(&B[(size_t)ai * ldb + kn + aw + 4]);
            } else {
                bv0 = *reinterpret_cast<const float4*>(&B[(size_t)(kn + br) * ldb + bc]);
                bv1 = *reinterpret_cast<const float4*>(&B[(size_t)(kn + 8 + br) * ldb + bc]);
            }
        }
        const float (*Ac)[132] = As[cur];
        const float (*Bc)[132] = Bs[cur];
        #pragma unroll
        for (int kk = 0; kk < 16; kk++) {
            float4 a0 = *reinterpret_cast<const float4*>(&Ac[kk][ty * 8]);
            float4 a1 = *reinterpret_cast<const float4*>(&Ac[kk][ty * 8 + 4]);
            float4 b0 = *reinterpret_cast<const float4*>(&Bc[kk][tx * 8]);
            float4 b1 = *reinterpret_cast<const float4*>(&Bc[kk][tx * 8 + 4]);
            float a[8] = {a0.x, a0.y, a0.z, a0.w, a1.x, a1.y, a1.z, a1.w};
            float b[8] = {b0.x, b0.y, b0.z, b0.w, b1.x, b1.y, b1.z, b1.w};
            #pragma unroll
            for (int i = 0; i < 8; i++)
                #pragma unroll
                for (int j = 0; j < 8; j++) acc[i][j] += a[i] * b[j];
        }
        if (more) {
            float (*Aw)[132] = As[cur ^ 1];
            float (*Bw)[132] = Bs[cur ^ 1];
            Aw[aw + 0][ai] = av0.x; Aw[aw + 1][ai] = av0.y;
            Aw[aw + 2][ai] = av0.z; Aw[aw + 3][ai] = av0.w;
            Aw[aw + 4][ai] = av1.x; Aw[aw + 5][ai] = av1.y;
            Aw[aw + 6][ai] = av1.z; Aw[aw + 7][ai] = av1.w;
            if (BT) {
                Bw[aw + 0][ai] = bv0.x; Bw[aw + 1][ai] = bv0.y;
                Bw[aw + 2][ai] = bv0.z; Bw[aw + 3][ai] = bv0.w;
                Bw[aw + 4][ai] = bv1.x; Bw[aw + 5][ai] = bv1.y;
                Bw[aw + 6][ai] = bv1.z; Bw[aw + 7][ai] = bv1.w;
            } else {
                *reinterpret_cast<float4*>(&Bw[br][bc]) = bv0;
                *reinterpret_cast<float4*>(&Bw[br + 8][bc]) = bv1;
            }
            __syncthreads();
            cur ^= 1;
        }
    }
}

// ---------------- general tiled GEMM (panel TRSM / SYRK) -------------------
// MODE 0: C -= AB   MODE 1: C = AB
template <int BT, int MODE>
__global__ __launch_bounds__(256, 2)
void gemm_kernel(const float* __restrict__ A, int lda,
                 const float* __restrict__ B, int ldb,
                 float* __restrict__ C, int ldc, int K, int triSkip) {
    extern __shared__ float sm[];
    const int bx = blockIdx.x, by = blockIdx.y;
    if (triSkip && by < bx) return;
    const int r0 = by * 128, c0 = bx * 128;

    float acc[8][8];
    #pragma unroll
    for (int i = 0; i < 8; i++)
        #pragma unroll
        for (int j = 0; j < 8; j++) acc[i][j] = 0.0f;

    const float* At = A + (size_t)r0 * lda;
    const float* Bt = BT ? (B + (size_t)c0 * ldb) : (B + c0);
    gemm_db<BT>(sm, At, lda, Bt, ldb, acc, K);

    const int tx = threadIdx.x & 15, ty = threadIdx.x >> 4;
    #pragma unroll
    for (int i = 0; i < 8; i++) {
        size_t base = (size_t)(r0 + ty * 8 + i) * ldc + c0 + tx * 8;
        #pragma unroll
        for (int j = 0; j < 8; j++) {
            if (MODE == 0) C[base + j] -= acc[i][j];
            else C[base + j] = acc[i][j];
        }
    }
}

// ---------------- F/G precompute INTO g_M ----------------------------------
// lower (i,j), i>j:  G_{i,j}=Linv_i*L_{i,j} -> upper (j,i);
//                    F_{i,j}=L_{i,j}*Linv_j -> in place (i,j).
__global__ __launch_bounds__(256, 2) void fg_kernel() {
    extern __shared__ float sm[];
    const int j = blockIdx.x, i = blockIdx.y;
    if (i <= j) return;
    float* Lij = g_M + (size_t)i * NB * N_DIM + (size_t)j * NB;
    const int tx = threadIdx.x & 15, ty = threadIdx.x >> 4;

    float acc[8][8];
    #pragma unroll
    for (int a = 0; a < 8; a++)
        #pragma unroll
        for (int b = 0; b < 8; b++) acc[a][b] = 0.0f;
    gemm_db<0>(sm, g_Linv + (size_t)i * NB * NB, NB, Lij, N_DIM, acc, NB);
    float* Gdst = g_M + (size_t)j * NB * N_DIM + (size_t)i * NB;
    #pragma unroll
    for (int a = 0; a < 8; a++) {
        size_t base = (size_t)(ty * 8 + a) * N_DIM + tx * 8;
        #pragma unroll
        for (int b = 0; b < 8; b++) Gdst[base + b] = acc[a][b];
    }
    __syncthreads();

    #pragma unroll
    for (int a = 0; a < 8; a++)
        #pragma unroll
        for (int b = 0; b < 8; b++) acc[a][b] = 0.0f;
    gemm_db<0>(sm, Lij, N_DIM, g_Linv + (size_t)j * NB * NB, NB, acc, NB);
    #pragma unroll
    for (int a = 0; a < 8; a++) {
        size_t base = (size_t)(ty * 8 + a) * N_DIM + tx * 8;
        #pragma unroll
        for (int b = 0; b < 8; b++) Lij[base + b] = acc[a][b];
    }
}

// ---------------- grid-wide barrier (co-resident grid only) ----------------
// Safe: PERS_BLOCKS=128 blocks x 256thr x 33.8KB smem all fit in wave 1 on
// 148 SMs, so every block is resident before any spin begins.
__device__ __forceinline__ void grid_bar(int idx) {
    __syncthreads();
    if (threadIdx.x == 0) {
        __threadfence();
        atomicAdd(&g_bar[idx], 1u);
        while (((volatile unsigned int*)g_bar)[idx] < gridDim.x) {
            __nanosleep(64);
        }
        __threadfence();
    }
    __syncthreads();
}

// ---------------- persistent solve kernel ----------------------------------
// ONE launch for: X1=K; 2x{forward 32 steps; backward 32 steps}; residual;
// finish. 128 blocks (co-resident on 148 SMs), 256 threads, 33792 B smem.
__global__ __launch_bounds__(256)
void solve_all_kernel(const float* __restrict__ Kb, const float* __restrict__ Phi,
                      const float* __restrict__ a_p, float* __restrict__ out) {
    extern __shared__ float sm[];
    const int bid = blockIdx.x;   // 128
    const int tid = threadIdx.x;  // 256
    const int tx = tid & 15, ty = tid >> 4;
    int barIdx = 0;

    // step 0: X1 = K
    {
        size_t n4 = (size_t)B_DIM * N_DIM / 4;
        const float4* src = reinterpret_cast<const float4*>(Kb);
        float4* dst = reinterpret_cast<float4*>(g_X1);
        for (size_t i = (size_t)bid * 256 + tid; i < n4; i += (size_t)PERS_BLOCKS * 256)
            dst[i] = src[i];
    }
    grid_bar(barIdx++);

    for (int pass = 0; pass < 2; pass++) {
        // ---- forward: X1 (work) -> X2 (out) ----
        for (int k = 0; k < NPAN; k++) {
            int ntile = 4 * (NPAN - k);
            if (bid < ntile) {
                int bx = bid >> 2, by = bid & 3;
                const float* A = g_X1 + (size_t)(by * NB) * N_DIM + (size_t)k * NB;
                float acc[8][8];
                #pragma unroll
                for (int i = 0; i < 8; i++)
                    #pragma unroll
                    for (int j = 0; j < 8; j++) acc[i][j] = 0.0f;
                if (bx == 0) {
                    gemm_db<1>(sm, A, N_DIM, g_Linv + (size_t)k * NB * NB, NB, acc, NB);
                    float* C = g_X2 + (size_t)(by * NB) * N_DIM + (size_t)k * NB;
                    #pragma unroll
                    for (int i = 0; i < 8; i++) {
                        size_t base = (size_t)(ty * 8 + i) * N_DIM + tx * 8;
                        #pragma unroll
                        for (int j = 0; j < 8; j++) C[base + j] = acc[i][j];
                    }
                } else {
                    int t = k + bx;
                    gemm_db<1>(sm, A, N_DIM,
                               g_M + (size_t)t * NB * N_DIM + (size_t)k * NB, N_DIM,
                               acc, NB);
                    float* C = g_X1 + (size_t)(by * NB) * N_DIM + (size_t)t * NB;
                    #pragma unroll
                    for (int i = 0; i < 8; i++) {
                        size_t base = (size_t)(ty * 8 + i) * N_DIM + tx * 8;
                        #pragma unroll
                        for (int j = 0; j < 8; j++) C[base + j] -= acc[i][j];
                    }
                }
            }
            grid_bar(barIdx++);
        }
        // ---- backward: X2 (work) -> X3 (out; pass1 accumulates) ----
        for (int k = NPAN - 1; k >= 0; k--) {
            int ntile = 4 * (k + 1);
            if (bid < ntile) {
                int bx = bid >> 2, by = bid & 3;
                const float* A = g_X2 + (size_t)(by * NB) * N_DIM + (size_t)k * NB;
                float acc[8][8];
                #pragma unroll
                for (int i = 0; i < 8; i++)
                    #pragma unroll
                    for (int j = 0; j < 8; j++) acc[i][j] = 0.0f;
                if (bx == k) {
                    gemm_db<0>(sm, A, N_DIM, g_Linv + (size_t)k * NB * NB, NB, acc, NB);
                    float* C = g_X3 + (size_t)(by * NB) * N_DIM + (size_t)k * NB;
                    #pragma unroll
                    for (int i = 0; i < 8; i++) {
                        size_t base = (size_t)(ty * 8 + i) * N_DIM + tx * 8;
                        #pragma unroll
                        for (int j = 0; j < 8; j++) {
                            if (pass) C[base + j] += acc[i][j];
                            else C[base + j] = acc[i][j];
                        }
                    }
                } else {
                    gemm_db<0>(sm, A, N_DIM,
                               g_M + (size_t)bx * NB * N_DIM + (size_t)k * NB, N_DIM,
                               acc, NB);
                    float* C = g_X2 + (size_t)(by * NB) * N_DIM + (size_t)bx * NB;
                    #pragma unroll
                    for (int i = 0; i < 8; i++) {
                        size_t base = (size_t)(ty * 8 + i) * N_DIM + tx * 8;
                        #pragma unroll
                        for (int j = 0; j < 8; j++) C[base + j] -= acc[i][j];
                    }
                }
            }
            grid_bar(barIdx++);
        }
        if (pass == 0) {
            // ---- residual: X1 = Kb - c1*X3*Phi - c2*X3  (128 tiles) ----
            int bx = bid >> 2, by = bid & 3;  // bx 0..31, by 0..3
            int r0 = by * 128, c0 = bx * 128;
            float acc[8][8];
            #pragma unroll
            for (int i = 0; i < 8; i++)
                #pragma unroll
                for (int j = 0; j < 8; j++) acc[i][j] = 0.0f;
            gemm_db<0>(sm, g_X3 + (size_t)r0 * N_DIM, N_DIM, Phi + c0, N_DIM,
                       acc, N_DIM);
            const float c1 = g_scal[0], c2 = g_scal[1];
            #pragma unroll
            for (int i = 0; i < 8; i++) {
                size_t base = (size_t)(r0 + ty * 8 + i) * N_DIM + c0 + tx * 8;
                #pragma unroll
                for (int j = 0; j < 8; j++)
                    g_X1[base + j] = Kb[base + j] - c1 * acc[i][j] - c2 * g_X3[base + j];
            }
            grid_bar(barIdx++);
        }
    }

    // ---- finish: out = X3 row / (a * <X3 row, K row>), 4 rows per block ----
    {
        float* red = sm;         // 8 warp partials
        float* dshp = sm + 8;    // broadcast slot
        const float a_val = a_p[0];
        for (int rr = 0; rr < 4; rr++) {
            int row = bid * 4 + rr;
            const float* z = &g_X3[(size_t)row * N_DIM];
            const float* kk = &Kb[(size_t)row * N_DIM];
            float s = 0.0f;
            for (int j = tid; j < N_DIM; j += 256) s += z[j] * kk[j];
            #pragma unroll
            for (int o = 16; o > 0; o >>= 1)
                s += __shfl_down_sync(0xffffffffu, s, o);
            if ((tid & 31) == 0) red[tid >> 5] = s;
            __syncthreads();
            if (tid == 0) {
                float t = 0.0f;
                #pragma unroll
                for (int w = 0; w < 8; w++) t += red[w];
                dshp[0] = 1.0f / (a_val * t);
            }
            __syncthreads();
            float d = dshp[0];
            for (int j = tid; j < N_DIM; j += 256)
                out[(size_t)row * N_DIM + j] = z[j] * d;
            __syncthreads();
        }
    }
}

// ---------------- host orchestration --------------------------------------
extern "C" void kernel_launch(void* const* d_in, const int* in_sizes, int n_in,
                              void* d_out, int out_size) {
    // Bind inputs BY SIZE (robust to metadata ordering).
    const float* Kb = nullptr;
    const float* Phi = nullptr;
    const float* v1024a = nullptr;
    const float* v1024b = nullptr;
    const float* a_p = nullptr;
    const float* gam = nullptr;
    for (int i = 0; i < n_in; i++) {
        int sz = in_sizes[i];
        const float* p = (const float*)d_in[i];
        if (sz == N_DIM * N_DIM) Phi = p;
        else if (sz == B_DIM * N_DIM) Kb = p;
        else if (sz == 1024) { if (!v1024a) v1024a = p; else v1024b = p; }
        else if (sz == 1) { if (!a_p) a_p = p; else gam = p; }
    }
    (void)out_size;

    const int dynSmemDiag = 2 * 128 * 129 * (int)sizeof(float);  // ~132 KB
    cudaFuncSetAttribute(chol_diag_kernel,
                         cudaFuncAttributeMaxDynamicSharedMemorySize, dynSmemDiag);

    float* pM;
    float* pLinv;
    cudaGetSymbolAddress((void**)&pM, g_M);
    cudaGetSymbolAddress((void**)&pLinv, g_Linv);

    scalars_kernel<<<1, 1024>>>(v1024a, v1024b, gam);
    build_M_kernel<<<4096, 256>>>(Phi);

    // blocked right-looking Cholesky (panel-blocked diag, R13 GEMMs)
    for (int k = 0; k < NPAN; k++) {
        chol_diag_kernel<<<1, 1024, dynSmemDiag>>>(k);
        int nt = NPAN - 1 - k;
        if (nt > 0) {
            float* A21 = pM + (size_t)(k + 1) * NB * N_DIM + (size_t)k * NB;
            dim3 gp(1, nt);   // panel: L21 = A21 * Linv_k^T (in place)
            gemm_kernel<1, 1><<<gp, 256, SMEM_GEMM>>>(
                A21, N_DIM, pLinv + (size_t)k * NB * NB, NB, A21, N_DIM, NB, 0);
            float* C22 = pM + (size_t)(k + 1) * NB * N_DIM + (size_t)(k + 1) * NB;
            dim3 gs(nt, nt);  // SYRK (lower tiles only)
            gemm_kernel<1, 0><<<gs, 256, SMEM_GEMM>>>(
                A21, N_DIM, A21, N_DIM, C22, N_DIM, NB, 1);
        }
    }

    // F (lower, in place) and G (upper) panels: one wide launch
    fg_kernel<<<dim3(NPAN, NPAN), 256, SMEM_GEMM>>>();

    // everything else: ONE persistent launch (solve1, IR residual+solve2, finish)
    solve_all_kernel<<<PERS_BLOCKS, 256, SMEM_GEMM>>>(Kb, Phi, a_p, (float*)d_out);
}

// round 15
// speedup vs baseline: 1.4351x; 1.1454x over previous
#include <cuda_runtime.h>
#include <math.h>
#include <stdint.h>

#define N_DIM 4096
#define B_DIM 512
#define NB 128
#define NPAN (N_DIM / NB)
#define PERS_BLOCKS 128
#define SMEM_GEMM (4 * 16 * 132 * (int)sizeof(float))   // 33792 B (256-thr gemm_db)
#define SMEM_G1K (2 * 32 * 132 * (int)sizeof(float))    // 33792 B (1024-thr gemm1k)
#define SMEM_CHOL (2 * 128 * 129 * (int)sizeof(float))  // 132096 B
#define SOLVE_BAR_BASE 96

// ---------------- device scratch ------------------------------------------
__device__ float g_M[(size_t)N_DIM * N_DIM];   // 64 MB: M -> L -> F(lower)/G(upper)
__device__ float g_Linv[NPAN * NB * NB];       // 2 MB: diag-block inverses
__device__ float g_X1[(size_t)B_DIM * N_DIM];  // 8 MB workspaces
__device__ float g_X2[(size_t)B_DIM * N_DIM];
__device__ float g_X3[(size_t)B_DIM * N_DIM];
__device__ float g_scal[4];                    // c1, c2
__device__ unsigned int g_bar[256];            // grid-barrier counters

// ---------------- scalars + barrier reset ----------------------------------
__global__ void scalars_kernel(const float* __restrict__ imp,
                               const float* __restrict__ exc,
                               const float* __restrict__ gamma_p) {
    __shared__ float red[32];
    int tid = threadIdx.x;  // 1024
    if (tid < 256) g_bar[tid] = 0u;
    float v = imp[tid] * imp[tid] + exc[tid] * exc[tid];
    #pragma unroll
    for (int o = 16; o > 0; o >>= 1) v += __shfl_down_sync(0xffffffffu, v, o);
    if ((tid & 31) == 0) red[tid >> 5] = v;
    __syncthreads();
    if (tid < 32) {
        float s = red[tid];
        #pragma unroll
        for (int o = 16; o > 0; o >>= 1) s += __shfl_down_sync(0xffffffffu, s, o);
        if (tid == 0) {
            g_scal[0] = s / (float)B_DIM;
            g_scal[1] = gamma_p[0] / (float)B_DIM;
        }
    }
}

// ---------------- build M = c1*Phi + c2*I ---------------------------------
__global__ void build_M_kernel(const float* __restrict__ Phi) {
    const float c1 = g_scal[0], c2 = g_scal[1];
    size_t total = (size_t)N_DIM * N_DIM;
    for (size_t i = (size_t)blockIdx.x * blockDim.x + threadIdx.x; i < total;
         i += (size_t)gridDim.x * blockDim.x) {
        float v = c1 * Phi[i];
        if ((i >> 12) == (i & 4095)) v += c2;
        g_M[i] = v;
    }
}

// ---------------- grid-wide barrier (co-resident grids only) ---------------
__device__ __forceinline__ void grid_bar(int idx) {
    __syncthreads();
    if (threadIdx.x == 0) {
        __threadfence();
        atomicAdd(&g_bar[idx], 1u);
        while (((volatile unsigned int*)g_bar)[idx] < gridDim.x) {
            __nanosleep(64);
        }
        __threadfence();
    }
    __syncthreads();
}

// ---------------- 1024-thread 128x128 tile GEMM (4x4 microtile) ------------
// sm: >= 33792 B. BT=1: acc += A(128xK)*B(128xK)^T ; BT=0: acc += A*B(Kx128).
// K multiple of 32.
template <int BT>
__device__ __forceinline__ void gemm1k(float* sm, const float* __restrict__ A,
                                       int lda, const float* __restrict__ B,
                                       int ldb, float acc[4][4], int K) {
    float (*As)[132] = reinterpret_cast<float (*)[132]>(sm);
    float (*Bs)[132] = reinterpret_cast<float (*)[132]>(sm + 32 * 132);
    const int tid = threadIdx.x;      // 1024
    const int ty = tid >> 5, tx = tid & 31;
    const int ar = tid >> 3;          // 0..127
    const int ac = (tid & 7) << 2;    // 0..28
    const int br = tid >> 5;          // 0..31
    const int bc = (tid & 31) << 2;   // 0..124
    for (int k0 = 0; k0 < K; k0 += 32) {
        __syncthreads();
        float4 av = *reinterpret_cast<const float4*>(&A[(size_t)ar * lda + k0 + ac]);
        As[ac + 0][ar] = av.x; As[ac + 1][ar] = av.y;
        As[ac + 2][ar] = av.z; As[ac + 3][ar] = av.w;
        if (BT) {
            float4 bv = *reinterpret_cast<const float4*>(&B[(size_t)ar * ldb + k0 + ac]);
            Bs[ac + 0][ar] = bv.x; Bs[ac + 1][ar] = bv.y;
            Bs[ac + 2][ar] = bv.z; Bs[ac + 3][ar] = bv.w;
        } else {
            float4 bv = *reinterpret_cast<const float4*>(&B[(size_t)(k0 + br) * ldb + bc]);
            *reinterpret_cast<float4*>(&Bs[br][bc]) = bv;
        }
        __syncthreads();
        #pragma unroll
        for (int kk = 0; kk < 32; kk++) {
            float4 a = *reinterpret_cast<const float4*>(&As[kk][ty * 4]);
            float4 b = *reinterpret_cast<const float4*>(&Bs[kk][tx * 4]);
            float aa[4] = {a.x, a.y, a.z, a.w};
            float bb[4] = {b.x, b.y, b.z, b.w};
            #pragma unroll
            for (int i = 0; i < 4; i++)
                #pragma unroll
                for (int j = 0; j < 4; j++) acc[i][j] += aa[i] * bb[j];
        }
    }
}

// mode 0: C = acc, 1: C -= acc, 2: C += acc   (1024-thread tile writer)
__device__ __forceinline__ void store1k(float* C, int ldc, float acc[4][4],
                                        int mode) {
    const int ty = threadIdx.x >> 5, tx = threadIdx.x & 31;
    #pragma unroll
    for (int i = 0; i < 4; i++) {
        float* p = &C[(size_t)(ty * 4 + i) * ldc + tx * 4];
        if (mode == 0) {
            float4 v = make_float4(acc[i][0], acc[i][1], acc[i][2], acc[i][3]);
            *reinterpret_cast<float4*>(p) = v;
        } else {
            float4 v = *reinterpret_cast<float4*>(p);
            if (mode == 1) { v.x -= acc[i][0]; v.y -= acc[i][1]; v.z -= acc[i][2]; v.w -= acc[i][3]; }
            else           { v.x += acc[i][0]; v.y += acc[i][1]; v.z += acc[i][2]; v.w += acc[i][3]; }
            *reinterpret_cast<float4*>(p) = v;
        }
    }
}

// ---------------- panel-blocked diag Cholesky + inverse (device fn) --------
// 1024 threads of ONE block; sh >= 2*128*129 floats.  [R14-proven body]
__device__ void diag_factor_invert(int k, float* sh) {
    float* s = sh;
    float* xs = sh + 128 * 129;
    __shared__ float Wt[32 * 33];
    const int tid = threadIdx.x;
    const int warp = tid >> 5, lane = tid & 31;
    float* blk = &g_M[(size_t)(k * NB) * N_DIM + (size_t)k * NB];

    for (int idx = tid; idx < NB * NB; idx += 1024) {
        int r = idx >> 7, c = idx & 127;
        s[r * 129 + c] = blk[(size_t)r * N_DIM + c];
    }
    __syncthreads();

    for (int p0 = 0; p0 < NB; p0 += 32) {
        if (warp == 0) {
            const int R = p0 + lane;
            for (int j = 0; j < 32; j++) {
                if (lane == j) s[R * 129 + p0 + j] = sqrtf(s[R * 129 + p0 + j]);
                __syncwarp();
                float dinv = 1.0f / s[(p0 + j) * 129 + p0 + j];
                if (lane > j) s[R * 129 + p0 + j] *= dinv;
                __syncwarp();
                if (lane > j) {
                    float lij = s[R * 129 + p0 + j];
                    for (int c = j + 1; c <= lane; c++)
                        s[R * 129 + p0 + c] -= lij * s[(p0 + c) * 129 + p0 + j];
                }
                __syncwarp();
            }
        }
        __syncthreads();
        const int nrows = NB - (p0 + 32);
        if (tid < nrows) {
            const int R = p0 + 32 + tid;
            for (int j = 0; j < 32; j++) {
                float sum = s[R * 129 + p0 + j];
                for (int c = 0; c < j; c++)
                    sum -= s[R * 129 + p0 + c] * s[(p0 + j) * 129 + p0 + c];
                s[R * 129 + p0 + j] = sum / s[(p0 + j) * 129 + p0 + j];
            }
        }
        __syncthreads();
        if (nrows > 0) {
            int tot = nrows * nrows;
            for (int t = tid; t < tot; t += 1024) {
                int i = t / nrows, j = t % nrows;
                int R = p0 + 32 + i, C = p0 + 32 + j;
                float sum = 0.0f;
                #pragma unroll 8
                for (int jj = 0; jj < 32; jj++)
                    sum += s[R * 129 + p0 + jj] * s[C * 129 + p0 + jj];
                s[R * 129 + C] -= sum;
            }
        }
        __syncthreads();
    }

    for (int idx = tid; idx < NB * NB; idx += 1024) {
        int r = idx >> 7, c = idx & 127;
        blk[(size_t)r * N_DIM + c] = s[r * 129 + c];
    }

    if (warp < 4) {
        const int b0 = warp * 32;
        const int c = lane;
        for (int j = 0; j < 32; j++) {
            float val = 0.0f;
            if (j >= c) {
                float sum = (j == c) ? 1.0f : 0.0f;
                for (int p = c; p < j; p++)
                    sum -= s[(b0 + j) * 129 + b0 + p] * xs[(b0 + p) * 129 + b0 + c];
                val = sum / s[(b0 + j) * 129 + b0 + j];
            }
            xs[(b0 + j) * 129 + b0 + c] = val;
        }
    }
    __syncthreads();

    {
        const int i = tid >> 5, j = tid & 31;
        for (int d = 1; d < 4; d++) {
            for (int q = 0; q + d < 4; q++) {
                const int p = q + d;
                float sum = 0.0f;
                for (int r = q; r < p; r++) {
                    float ss = 0.0f;
                    #pragma unroll 8
                    for (int kk = 0; kk < 32; kk++)
                        ss += s[(p * 32 + i) * 129 + r * 32 + kk] *
                              xs[(r * 32 + kk) * 129 + q * 32 + j];
                    sum += ss;
                }
                Wt[i * 33 + j] = sum;
                __syncthreads();
                float acc = 0.0f;
                #pragma unroll 8
                for (int kk = 0; kk < 32; kk++)
                    acc += xs[(p * 32 + i) * 129 + p * 32 + kk] * Wt[kk * 33 + j];
                __syncthreads();
                xs[(p * 32 + i) * 129 + q * 32 + j] = -acc;
                __syncthreads();
            }
        }
    }

    float* go = &g_Linv[(size_t)k * NB * NB];
    for (int idx = tid; idx < NB * NB; idx += 1024) {
        int r = idx >> 7, c = idx & 127;
        go[idx] = (r >= c) ? xs[r * 129 + c] : 0.0f;
    }
}

// ---------------- persistent Cholesky (one launch, 94 grid barriers) -------
// 128 blocks x 1024 thr, 132KB smem -> 1 block/SM, co-resident on 148 SMs.
// Lookahead: diag(k+1) on block 0 runs concurrently with SYRK-rest.
__global__ __launch_bounds__(1024, 1)
void chol_all_kernel() {
    extern __shared__ float sh[];
    const int bid = blockIdx.x;
    int bi = 0;

    if (bid == 0) diag_factor_invert(0, sh);
    grid_bar(bi++);

    for (int k = 0; k < NPAN - 1; k++) {
        const int nt = NPAN - 1 - k;  // trailing rows k+1..31
        // panel: L(t,k) = A(t,k) * Linv_k^T  (in place)
        for (int t = bid; t < nt; t += PERS_BLOCKS) {
            int row = k + 1 + t;
            float* Atile = g_M + (size_t)row * NB * N_DIM + (size_t)k * NB;
            float acc[4][4] = {};
            gemm1k<1>(sh, Atile, N_DIM, g_Linv + (size_t)k * NB * NB, NB, acc, NB);
            __syncthreads();  // all reads of Atile complete before overwrite
            store1k(Atile, N_DIM, acc, 0);
        }
        grid_bar(bi++);
        // SYRK column k+1: C(i,k+1) -= L(i,k) * L(k+1,k)^T
        {
            const float* Bp = g_M + (size_t)(k + 1) * NB * N_DIM + (size_t)k * NB;
            for (int t = bid; t < nt; t += PERS_BLOCKS) {
                int i = k + 1 + t;
                const float* Ap = g_M + (size_t)i * NB * N_DIM + (size_t)k * NB;
                float* Cp = g_M + (size_t)i * NB * N_DIM + (size_t)(k + 1) * NB;
                float acc[4][4] = {};
                gemm1k<1>(sh, Ap, N_DIM, Bp, N_DIM, acc, NB);
                __syncthreads();
                store1k(Cp, N_DIM, acc, 1);
            }
        }
        grid_bar(bi++);
        // lookahead: diag(k+1) on block 0; SYRK-rest (cols >= k+2) on others
        if (bid == 0) {
            diag_factor_invert(k + 1, sh);
        } else {
            const int nrest = (nt - 1) * nt / 2;  // pairs k+2<=j<=i<=31
            for (int t = bid - 1; t < nrest; t += PERS_BLOCKS - 1) {
                int j = k + 2, rem = t;
                while (rem >= (NPAN - j)) { rem -= (NPAN - j); j++; }
                int i = j + rem;
                const float* Ap = g_M + (size_t)i * NB * N_DIM + (size_t)k * NB;
                const float* Bp = g_M + (size_t)j * NB * N_DIM + (size_t)k * NB;
                float* Cp = g_M + (size_t)i * NB * N_DIM + (size_t)j * NB;
                float acc[4][4] = {};
                gemm1k<1>(sh, Ap, N_DIM, Bp, N_DIM, acc, NB);
                __syncthreads();
                store1k(Cp, N_DIM, acc, 1);
            }
        }
        grid_bar(bi++);
    }
}

// ---------------- 256-thread double-buffered GEMM (fg only) ----------------
template <int BT>
__device__ __forceinline__ void gemm_db(float* sm, const float* __restrict__ A,
                                        int lda, const float* __restrict__ B,
                                        int ldb, float acc[8][8], int K) {
    float (*As)[16][132] = reinterpret_cast<float (*)[16][132]>(sm);
    float (*Bs)[16][132] = reinterpret_cast<float (*)[16][132]>(sm + 2 * 16 * 132);
    const int tid = threadIdx.x;
    const int ai = tid >> 1;
    const int aw = (tid & 1) << 3;
    const int br = tid >> 5;
    const int bc = (tid & 31) << 2;
    const int ty = tid >> 4, tx = tid & 15;

    float4 av0, av1, bv0, bv1;
    av0 = *reinterpret_cast<const float4*>(&A[(size_t)ai * lda + aw]);
    av1 = *reinterpret_cast<const float4*>(&A[(size_t)ai * lda + aw + 4]);
    if (BT) {
        bv0 = *reinterpret_cast<const float4*>(&B[(size_t)ai * ldb + aw]);
        bv1 = *reinterpret_cast<const float4*>(&B[(size_t)ai * ldb + aw + 4]);
    } else {
        bv0 = *reinterpret_cast<const float4*>(&B[(size_t)br * ldb + bc]);
        bv1 = *reinterpret_cast<const float4*>(&B[(size_t)(br + 8) * ldb + bc]);
    }
    {
        float (*Aw)[132] = As[0];
        float (*Bw)[132] = Bs[0];
        Aw[aw + 0][ai] = av0.x; Aw[aw + 1][ai] = av0.y;
        Aw[aw + 2][ai] = av0.z; Aw[aw + 3][ai] = av0.w;
        Aw[aw + 4][ai] = av1.x; Aw[aw + 5][ai] = av1.y;
        Aw[aw + 6][ai] = av1.z; Aw[aw + 7][ai] = av1.w;
        if (BT) {
            Bw[aw + 0][ai] = bv0.x; Bw[aw + 1][ai] = bv0.y;
            Bw[aw + 2][ai] = bv0.z; Bw[aw + 3][ai] = bv0.w;
            Bw[aw + 4][ai] = bv1.x; Bw[aw + 5][ai] = bv1.y;
            Bw[aw + 6][ai] = bv1.z; Bw[aw + 7][ai] = bv1.w;
        } else {
            *reinterpret_cast<float4*>(&Bw[br][bc]) = bv0;
            *reinterpret_cast<float4*>(&Bw[br + 8][bc]) = bv1;
        }
    }
    __syncthreads();

    int cur = 0;
    for (int k0 = 0; k0 < K; k0 += 16) {
        const bool more = (k0 + 16) < K;
        if (more) {
            const int kn = k0 + 16;
            av0 = *reinterpret_cast<const float4*>(&A[(size_t)ai * lda + kn + aw]);
            av1 = *reinterpret_cast<const float4*>(&A[(size_t)ai * lda + kn + aw + 4]);
            if (BT) {
                bv0 = *reinterpret_cast<const float4*>(&B[(size_t)ai * ldb + kn + aw]);
                bv1 = *reinterpret_cast<const float4*>(&B[(size_t)ai * ldb + kn + aw + 4]);
            } else {
                bv0 = *reinterpret_cast<const float4*>(&B[(size_t)(kn + br) * ldb + bc]);
                bv1 = *reinterpret_cast<const float4*>(&B[(size_t)(kn + 8 + br) * ldb + bc]);
            }
        }
        const float (*Ac)[132] = As[cur];
        const float (*Bc)[132] = Bs[cur];
        #pragma unroll
        for (int kk = 0; kk < 16; kk++) {
            float4 a0 = *reinterpret_cast<const float4*>(&Ac[kk][ty * 8]);
            float4 a1 = *reinterpret_cast<const float4*>(&Ac[kk][ty * 8 + 4]);
            float4 b0 = *reinterpret_cast<const float4*>(&Bc[kk][tx * 8]);
            float4 b1 = *reinterpret_cast<const float4*>(&Bc[kk][tx * 8 + 4]);
            float a[8] = {a0.x, a0.y, a0.z, a0.w, a1.x, a1.y, a1.z, a1.w};
            float b[8] = {b0.x, b0.y, b0.z, b0.w, b1.x, b1.y, b1.z, b1.w};
            #pragma unroll
            for (int i = 0; i < 8; i++)
                #pragma unroll
                for (int j = 0; j < 8; j++) acc[i][j] += a[i] * b[j];
        }
        if (more) {
            float (*Aw)[132] = As[cur ^ 1];
            float (*Bw)[132] = Bs[cur ^ 1];
            Aw[aw + 0][ai] = av0.x; Aw[aw + 1][ai] = av0.y;
            Aw[aw + 2][ai] = av0.z; Aw[aw + 3][ai] = av0.w;
            Aw[aw + 4][ai] = av1.x; Aw[aw + 5][ai] = av1.y;
            Aw[aw + 6][ai] = av1.z; Aw[aw + 7][ai] = av1.w;
            if (BT) {
                Bw[aw + 0][ai] = bv0.x; Bw[aw + 1][ai] = bv0.y;
                Bw[aw + 2][ai] = bv0.z; Bw[aw + 3][ai] = bv0.w;
                Bw[aw + 4][ai] = bv1.x; Bw[aw + 5][ai] = bv1.y;
                Bw[aw + 6][ai] = bv1.z; Bw[aw + 7][ai] = bv1.w;
            } else {
                *reinterpret_cast<float4*>(&Bw[br][bc]) = bv0;
                *reinterpret_cast<float4*>(&Bw[br + 8][bc]) = bv1;
            }
            __syncthreads();
            cur ^= 1;
        }
    }
}

// ---------------- F/G precompute INTO g_M (wide launch, 256 thr) -----------
__global__ __launch_bounds__(256, 2) void fg_kernel() {
    extern __shared__ float sm[];
    const int j = blockIdx.x, i = blockIdx.y;
    if (i <= j) return;
    float* Lij = g_M + (size_t)i * NB * N_DIM + (size_t)j * NB;
    const int tx = threadIdx.x & 15, ty = threadIdx.x >> 4;

    float acc[8][8];
    #pragma unroll
    for (int a = 0; a < 8; a++)
        #pragma unroll
        for (int b = 0; b < 8; b++) acc[a][b] = 0.0f;
    gemm_db<0>(sm, g_Linv + (size_t)i * NB * NB, NB, Lij, N_DIM, acc, NB);
    float* Gdst = g_M + (size_t)j * NB * N_DIM + (size_t)i * NB;
    #pragma unroll
    for (int a = 0; a < 8; a++) {
        size_t base = (size_t)(ty * 8 + a) * N_DIM + tx * 8;
        #pragma unroll
        for (int b = 0; b < 8; b++) Gdst[base + b] = acc[a][b];
    }
    __syncthreads();

    #pragma unroll
    for (int a = 0; a < 8; a++)
        #pragma unroll
        for (int b = 0; b < 8; b++) acc[a][b] = 0.0f;
    gemm_db<0>(sm, Lij, N_DIM, g_Linv + (size_t)j * NB * NB, NB, acc, NB);
    #pragma unroll
    for (int a = 0; a < 8; a++) {
        size_t base = (size_t)(ty * 8 + a) * N_DIM + tx * 8;
        #pragma unroll
        for (int b = 0; b < 8; b++) Lij[base + b] = acc[a][b];
    }
}

// ---------------- persistent solve (1024 thr, gemm1k) ----------------------
__global__ __launch_bounds__(1024, 1)
void solve_all_kernel(const float* __restrict__ Kb, const float* __restrict__ Phi,
                      const float* __restrict__ a_p, float* __restrict__ out) {
    extern __shared__ float sm[];
    const int bid = blockIdx.x;   // 128
    const int tid = threadIdx.x;  // 1024
    int barIdx = SOLVE_BAR_BASE;

    // X1 = K
    {
        size_t n4 = (size_t)B_DIM * N_DIM / 4;
        const float4* src = reinterpret_cast<const float4*>(Kb);
        float4* dst = reinterpret_cast<float4*>(g_X1);
        for (size_t i = (size_t)bid * 1024 + tid; i < n4;
             i += (size_t)PERS_BLOCKS * 1024)
            dst[i] = src[i];
    }
    grid_bar(barIdx++);

    for (int pass = 0; pass < 2; pass++) {
        // forward: X1 (work) -> X2 (out)
        for (int k = 0; k < NPAN; k++) {
            int ntile = 4 * (NPAN - k);
            if (bid < ntile) {
                int bx = bid >> 2, by = bid & 3;
                const float* A = g_X1 + (size_t)(by * NB) * N_DIM + (size_t)k * NB;
                float acc[4][4] = {};
                if (bx == 0) {
                    gemm1k<1>(sm, A, N_DIM, g_Linv + (size_t)k * NB * NB, NB, acc, NB);
                    store1k(g_X2 + (size_t)(by * NB) * N_DIM + (size_t)k * NB,
                            N_DIM, acc, 0);
                } else {
                    int t = k + bx;
                    gemm1k<1>(sm, A, N_DIM,
                              g_M + (size_t)t * NB * N_DIM + (size_t)k * NB, N_DIM,
                              acc, NB);
                    store1k(g_X1 + (size_t)(by * NB) * N_DIM + (size_t)t * NB,
                            N_DIM, acc, 1);
                }
            }
            grid_bar(barIdx++);
        }
        // backward: X2 (work) -> X3 (out; pass1 accumulates)
        for (int k = NPAN - 1; k >= 0; k--) {
            int ntile = 4 * (k + 1);
            if (bid < ntile) {
                int bx = bid >> 2, by = bid & 3;
                const float* A = g_X2 + (size_t)(by * NB) * N_DIM + (size_t)k * NB;
                float acc[4][4] = {};
                if (bx == k) {
                    gemm1k<0>(sm, A, N_DIM, g_Linv + (size_t)k * NB * NB, NB, acc, NB);
                    store1k(g_X3 + (size_t)(by * NB) * N_DIM + (size_t)k * NB,
                            N_DIM, acc, pass ? 2 : 0);
                } else {
                    gemm1k<0>(sm, A, N_DIM,
                              g_M + (size_t)bx * NB * N_DIM + (size_t)k * NB, N_DIM,
                              acc, NB);
                    store1k(g_X2 + (size_t)(by * NB) * N_DIM + (size_t)bx * NB,
                            N_DIM, acc, 1);
                }
            }
            grid_bar(barIdx++);
        }
        if (pass == 0) {
            // residual: X1 = Kb - c1*X3*Phi - c2*X3 (128 tiles, K=4096)
            int bx = bid >> 2, by = bid & 3;
            int r0 = by * 128, c0 = bx * 128;
            float acc[4][4] = {};
            gemm1k<0>(sm, g_X3 + (size_t)r0 * N_DIM, N_DIM, Phi + c0, N_DIM,
                      acc, N_DIM);
            const float c1 = g_scal[0], c2 = g_scal[1];
            const int ty = tid >> 5, tx = tid & 31;
            #pragma unroll
            for (int i = 0; i < 4; i++) {
                size_t base = (size_t)(r0 + ty * 4 + i) * N_DIM + c0 + tx * 4;
                #pragma unroll
                for (int j = 0; j < 4; j++)
                    g_X1[base + j] = Kb[base + j] - c1 * acc[i][j] - c2 * g_X3[base + j];
            }
            grid_bar(barIdx++);
        }
    }

    // finish: out = X3 row / (a * <X3 row, K row>), 4 rows per block
    {
        float* red = sm;       // 32 warp partials
        float* dshp = sm + 32;
        const float a_val = a_p[0];
        for (int rr = 0; rr < 4; rr++) {
            int row = bid * 4 + rr;
            const float* z = &g_X3[(size_t)row * N_DIM];
            const float* kk = &Kb[(size_t)row * N_DIM];
            float s = 0.0f;
            for (int j = tid; j < N_DIM; j += 1024) s += z[j] * kk[j];
            #pragma unroll
            for (int o = 16; o > 0; o >>= 1)
                s += __shfl_down_sync(0xffffffffu, s, o);
            if ((tid & 31) == 0) red[tid >> 5] = s;
            __syncthreads();
            if (tid == 0) {
                float t = 0.0f;
                #pragma unroll
                for (int w = 0; w < 32; w++) t += red[w];
                dshp[0] = 1.0f / (a_val * t);
            }
            __syncthreads();
            float d = dshp[0];
            for (int j = tid; j < N_DIM; j += 1024)
                out[(size_t)row * N_DIM + j] = z[j] * d;
            __syncthreads();
        }
    }
}

// ---------------- host orchestration --------------------------------------
extern "C" void kernel_launch(void* const* d_in, const int* in_sizes, int n_in,
                              void* d_out, int out_size) {
    // Bind inputs BY SIZE (robust to metadata ordering).
    const float* Kb = nullptr;
    const float* Phi = nullptr;
    const float* v1024a = nullptr;
    const float* v1024b = nullptr;
    const float* a_p = nullptr;
    const float* gam = nullptr;
    for (int i = 0; i < n_in; i++) {
        int sz = in_sizes[i];
        const float* p = (const float*)d_in[i];
        if (sz == N_DIM * N_DIM) Phi = p;
        else if (sz == B_DIM * N_DIM) Kb = p;
        else if (sz == 1024) { if (!v1024a) v1024a = p; else v1024b = p; }
        else if (sz == 1) { if (!a_p) a_p = p; else gam = p; }
    }
    (void)out_size;

    cudaFuncSetAttribute(chol_all_kernel,
                         cudaFuncAttributeMaxDynamicSharedMemorySize, SMEM_CHOL);
    cudaFuncSetAttribute(solve_all_kernel,
                         cudaFuncAttributeMaxDynamicSharedMemorySize, SMEM_G1K);

    scalars_kernel<<<1, 1024>>>(v1024a, v1024b, gam);
    build_M_kernel<<<4096, 256>>>(Phi);

    // whole blocked Cholesky: ONE persistent launch with lookahead
    chol_all_kernel<<<PERS_BLOCKS, 1024, SMEM_CHOL>>>();

    // F (lower, in place) and G (upper) panels: one wide launch
    fg_kernel<<<dim3(NPAN, NPAN), 256, SMEM_GEMM>>>();

    // solve1 + IR + finish: ONE persistent launch
    solve_all_kernel<<<PERS_BLOCKS, 1024, SMEM_G1K>>>(Kb, Phi, a_p, (float*)d_out);
}

// round 17
// speedup vs baseline: 1.4554x; 1.0141x over previous
#include <cuda_runtime.h>
#include <math.h>
#include <stdint.h>

#define N_DIM 4096
#define B_DIM 512
#define NB 128
#define NPAN (N_DIM / NB)
#define PERS_BLOCKS 128
#define SMEM_G1K (2 * 2 * 32 * 132 * (int)sizeof(float))  // 67584 B (db gemm1k)
#define SMEM_CHOL (2 * 128 * 129 * (int)sizeof(float))    // 132096 B
#define SOLVE_BAR_BASE 96

// ---------------- device scratch ------------------------------------------
__device__ float g_M[(size_t)N_DIM * N_DIM];   // 64 MB: M -> L -> F(lower)/G(upper)
__device__ float g_Linv[NPAN * NB * NB];       // 2 MB: diag-block inverses
__device__ float g_X1[(size_t)B_DIM * N_DIM];  // 8 MB workspaces
__device__ float g_X2[(size_t)B_DIM * N_DIM];
__device__ float g_X3[(size_t)B_DIM * N_DIM];
__device__ float g_scal[4];                    // c1, c2
__device__ unsigned int g_bar[256];            // grid-barrier counters

// ---------------- scalars + barrier reset ----------------------------------
__global__ void scalars_kernel(const float* __restrict__ imp,
                               const float* __restrict__ exc,
                               const float* __restrict__ gamma_p) {
    __shared__ float red[32];
    int tid = threadIdx.x;  // 1024
    if (tid < 256) g_bar[tid] = 0u;
    float v = imp[tid] * imp[tid] + exc[tid] * exc[tid];
    #pragma unroll
    for (int o = 16; o > 0; o >>= 1) v += __shfl_down_sync(0xffffffffu, v, o);
    if ((tid & 31) == 0) red[tid >> 5] = v;
    __syncthreads();
    if (tid < 32) {
        float s = red[tid];
        #pragma unroll
        for (int o = 16; o > 0; o >>= 1) s += __shfl_down_sync(0xffffffffu, s, o);
        if (tid == 0) {
            g_scal[0] = s / (float)B_DIM;
            g_scal[1] = gamma_p[0] / (float)B_DIM;
        }
    }
}

// ---------------- build M = c1*Phi + c2*I ---------------------------------
__global__ void build_M_kernel(const float* __restrict__ Phi) {
    const float c1 = g_scal[0], c2 = g_scal[1];
    size_t total = (size_t)N_DIM * N_DIM;
    for (size_t i = (size_t)blockIdx.x * blockDim.x + threadIdx.x; i < total;
         i += (size_t)gridDim.x * blockDim.x) {
        float v = c1 * Phi[i];
        if ((i >> 12) == (i & 4095)) v += c2;
        g_M[i] = v;
    }
}

// ---------------- grid-wide barrier (co-resident grids only) ---------------
__device__ __forceinline__ void grid_bar(int idx) {
    __syncthreads();
    if (threadIdx.x == 0) {
        __threadfence();
        atomicAdd(&g_bar[idx], 1u);
        while (((volatile unsigned int*)g_bar)[idx] < gridDim.x) {
            __nanosleep(64);
        }
        __threadfence();
    }
    __syncthreads();
}

// ---------------- 1024-thread DOUBLE-BUFFERED 128x128 tile GEMM ------------
// sm: >= 67584 B (2 buffers x (As+Bs)). BT=1: acc += A(128xK)*B(128xK)^T ;
// BT=0: acc += A(128xK)*B(Kx128). K multiple of 32. ONE sync per 32-K chunk;
// next chunk's global loads prefetched into registers during compute.
// Safety: writes to buffer X at chunk i+2 are separated from all reads of X
// at chunk i by the sync inside chunk i+1.
template <int BT>
__device__ __forceinline__ void gemm1k(float* sm, const float* __restrict__ A,
                                       int lda, const float* __restrict__ B,
                                       int ldb, float acc[4][4], int K) {
    const int tid = threadIdx.x;      // 1024
    const int ty = tid >> 5, tx = tid & 31;
    const int ar = tid >> 3;          // 0..127
    const int ac = (tid & 7) << 2;    // 0..28
    const int br = tid >> 5;          // 0..31
    const int bc = (tid & 31) << 2;   // 0..124

    float4 av, bv;
    av = *reinterpret_cast<const float4*>(&A[(size_t)ar * lda + ac]);
    if (BT) bv = *reinterpret_cast<const float4*>(&B[(size_t)ar * ldb + ac]);
    else    bv = *reinterpret_cast<const float4*>(&B[(size_t)br * ldb + bc]);

    int cur = 0;
    for (int k0 = 0; k0 < K; k0 += 32) {
        float (*As)[132] = reinterpret_cast<float (*)[132]>(sm + cur * (2 * 32 * 132));
        float (*Bs)[132] = reinterpret_cast<float (*)[132]>(sm + cur * (2 * 32 * 132) + 32 * 132);
        As[ac + 0][ar] = av.x; As[ac + 1][ar] = av.y;
        As[ac + 2][ar] = av.z; As[ac + 3][ar] = av.w;
        if (BT) {
            Bs[ac + 0][ar] = bv.x; Bs[ac + 1][ar] = bv.y;
            Bs[ac + 2][ar] = bv.z; Bs[ac + 3][ar] = bv.w;
        } else {
            *reinterpret_cast<float4*>(&Bs[br][bc]) = bv;
        }
        __syncthreads();
        if (k0 + 32 < K) {
            const int kn = k0 + 32;
            av = *reinterpret_cast<const float4*>(&A[(size_t)ar * lda + kn + ac]);
            if (BT) bv = *reinterpret_cast<const float4*>(&B[(size_t)ar * ldb + kn + ac]);
            else    bv = *reinterpret_cast<const float4*>(&B[(size_t)(kn + br) * ldb + bc]);
        }
        #pragma unroll
        for (int kk = 0; kk < 32; kk++) {
            float4 a = *reinterpret_cast<const float4*>(&As[kk][ty * 4]);
            float4 b = *reinterpret_cast<const float4*>(&Bs[kk][tx * 4]);
            float aa[4] = {a.x, a.y, a.z, a.w};
            float bb[4] = {b.x, b.y, b.z, b.w};
            #pragma unroll
            for (int i = 0; i < 4; i++)
                #pragma unroll
                for (int j = 0; j < 4; j++) acc[i][j] += aa[i] * bb[j];
        }
        cur ^= 1;
    }
}

// mode 0: C = acc, 1: C -= acc, 2: C += acc   (1024-thread tile writer)
__device__ __forceinline__ void store1k(float* C, int ldc, float acc[4][4],
                                        int mode) {
    const int ty = threadIdx.x >> 5, tx = threadIdx.x & 31;
    #pragma unroll
    for (int i = 0; i < 4; i++) {
        float* p = &C[(size_t)(ty * 4 + i) * ldc + tx * 4];
        if (mode == 0) {
            float4 v = make_float4(acc[i][0], acc[i][1], acc[i][2], acc[i][3]);
            *reinterpret_cast<float4*>(p) = v;
        } else {
            float4 v = *reinterpret_cast<float4*>(p);
            if (mode == 1) { v.x -= acc[i][0]; v.y -= acc[i][1]; v.z -= acc[i][2]; v.w -= acc[i][3]; }
            else           { v.x += acc[i][0]; v.y += acc[i][1]; v.z += acc[i][2]; v.w += acc[i][3]; }
            *reinterpret_cast<float4*>(p) = v;
        }
    }
}

// ---------------- fg pair for tile (i,j), i>j: G then F (one block) --------
// G_{i,j}=Linv_i*L_{i,j} -> upper (j,i);  F_{i,j}=L_{i,j}*Linv_j -> in place.
// REQUIRES all Linv final (runs only in the tail phase after factorization).
__device__ void fg_tile(float* sm, int i, int j) {
    float* Lij = g_M + (size_t)i * NB * N_DIM + (size_t)j * NB;
    float acc[4][4] = {};
    gemm1k<0>(sm, g_Linv + (size_t)i * NB * NB, NB, Lij, N_DIM, acc, NB);
    __syncthreads();
    store1k(g_M + (size_t)j * NB * N_DIM + (size_t)i * NB, N_DIM, acc, 0);
    __syncthreads();
    float acc2[4][4] = {};
    gemm1k<0>(sm, Lij, N_DIM, g_Linv + (size_t)j * NB * NB, NB, acc2, NB);
    __syncthreads();  // all reads of Lij done before in-place overwrite
    store1k(Lij, N_DIM, acc2, 0);
}

// ---------------- panel-blocked diag Cholesky + inverse (device fn) --------
// 1024 threads of ONE block; sh >= 2*128*129 floats.  [R14/R15-proven body]
__device__ void diag_factor_invert(int k, float* sh) {
    float* s = sh;
    float* xs = sh + 128 * 129;
    __shared__ float Wt[32 * 33];
    const int tid = threadIdx.x;
    const int warp = tid >> 5, lane = tid & 31;
    float* blk = &g_M[(size_t)(k * NB) * N_DIM + (size_t)k * NB];

    for (int idx = tid; idx < NB * NB; idx += 1024) {
        int r = idx >> 7, c = idx & 127;
        s[r * 129 + c] = blk[(size_t)r * N_DIM + c];
    }
    __syncthreads();

    for (int p0 = 0; p0 < NB; p0 += 32) {
        if (warp == 0) {
            const int R = p0 + lane;
            for (int j = 0; j < 32; j++) {
                if (lane == j) s[R * 129 + p0 + j] = sqrtf(s[R * 129 + p0 + j]);
                __syncwarp();
                float dinv = 1.0f / s[(p0 + j) * 129 + p0 + j];
                if (lane > j) s[R * 129 + p0 + j] *= dinv;
                __syncwarp();
                if (lane > j) {
                    float lij = s[R * 129 + p0 + j];
                    for (int c = j + 1; c <= lane; c++)
                        s[R * 129 + p0 + c] -= lij * s[(p0 + c) * 129 + p0 + j];
                }
                __syncwarp();
            }
        }
        __syncthreads();
        const int nrows = NB - (p0 + 32);
        if (tid < nrows) {
            const int R = p0 + 32 + tid;
            for (int j = 0; j < 32; j++) {
                float sum = s[R * 129 + p0 + j];
                for (int c = 0; c < j; c++)
                    sum -= s[R * 129 + p0 + c] * s[(p0 + j) * 129 + p0 + c];
                s[R * 129 + p0 + j] = sum / s[(p0 + j) * 129 + p0 + j];
            }
        }
        __syncthreads();
        if (nrows > 0) {
            int tot = nrows * nrows;
            for (int t = tid; t < tot; t += 1024) {
                int i = t / nrows, j = t % nrows;
                int R = p0 + 32 + i, C = p0 + 32 + j;
                float sum = 0.0f;
                #pragma unroll 8
                for (int jj = 0; jj < 32; jj++)
                    sum += s[R * 129 + p0 + jj] * s[C * 129 + p0 + jj];
                s[R * 129 + C] -= sum;
            }
        }
        __syncthreads();
    }

    for (int idx = tid; idx < NB * NB; idx += 1024) {
        int r = idx >> 7, c = idx & 127;
        blk[(size_t)r * N_DIM + c] = s[r * 129 + c];
    }

    if (warp < 4) {
        const int b0 = warp * 32;
        const int c = lane;
        for (int j = 0; j < 32; j++) {
            float val = 0.0f;
            if (j >= c) {
                float sum = (j == c) ? 1.0f : 0.0f;
                for (int p = c; p < j; p++)
                    sum -= s[(b0 + j) * 129 + b0 + p] * xs[(b0 + p) * 129 + b0 + c];
                val = sum / s[(b0 + j) * 129 + b0 + j];
            }
            xs[(b0 + j) * 129 + b0 + c] = val;
        }
    }
    __syncthreads();

    {
        const int i = tid >> 5, j = tid & 31;
        for (int d = 1; d < 4; d++) {
            for (int q = 0; q + d < 4; q++) {
                const int p = q + d;
                float sum = 0.0f;
                for (int r = q; r < p; r++) {
                    float ss = 0.0f;
                    #pragma unroll 8
                    for (int kk = 0; kk < 32; kk++)
                        ss += s[(p * 32 + i) * 129 + r * 32 + kk] *
                              xs[(r * 32 + kk) * 129 + q * 32 + j];
                    sum += ss;
                }
                Wt[i * 33 + j] = sum;
                __syncthreads();
                float acc = 0.0f;
                #pragma unroll 8
                for (int kk = 0; kk < 32; kk++)
                    acc += xs[(p * 32 + i) * 129 + p * 32 + kk] * Wt[kk * 33 + j];
                __syncthreads();
                xs[(p * 32 + i) * 129 + q * 32 + j] = -acc;
                __syncthreads();
            }
        }
    }

    float* go = &g_Linv[(size_t)k * NB * NB];
    for (int idx = tid; idx < NB * NB; idx += 1024) {
        int r = idx >> 7, c = idx & 127;
        go[idx] = (r >= c) ? xs[r * 129 + c] : 0.0f;
    }
}

// ---------------- persistent Cholesky, then tail F/G ------------------------
// 128 blocks x 1024 thr, 132KB smem -> 1 block/SM, co-resident on 148 SMs.
// Iteration k: panel | bar | syrk-col k+1 | bar |
//   { diag(k+1) on block 0  ||  syrk-rest on blocks 1..127 } | bar.
// Tail (after last barrier: ALL L columns and ALL Linv final): fg over all
// 496 tiles, grid-strided, mutually independent -> no further barriers.
__global__ __launch_bounds__(1024, 1)
void chol_all_kernel() {
    extern __shared__ float sh[];
    const int bid = blockIdx.x;
    int bi = 0;

    if (bid == 0) diag_factor_invert(0, sh);
    grid_bar(bi++);

    for (int k = 0; k < NPAN - 1; k++) {
        const int nt = NPAN - 1 - k;  // trailing rows k+1..31
        // panel: L(t,k) = A(t,k) * Linv_k^T  (in place)
        for (int t = bid; t < nt; t += PERS_BLOCKS) {
            int row = k + 1 + t;
            float* Atile = g_M + (size_t)row * NB * N_DIM + (size_t)k * NB;
            float acc[4][4] = {};
            gemm1k<1>(sh, Atile, N_DIM, g_Linv + (size_t)k * NB * NB, NB, acc, NB);
            __syncthreads();  // all reads of Atile complete before overwrite
            store1k(Atile, N_DIM, acc, 0);
            __syncthreads();
        }
        grid_bar(bi++);
        // SYRK column k+1: C(i,k+1) -= L(i,k) * L(k+1,k)^T
        {
            const float* Bp = g_M + (size_t)(k + 1) * NB * N_DIM + (size_t)k * NB;
            for (int t = bid; t < nt; t += PERS_BLOCKS) {
                int i = k + 1 + t;
                const float* Ap = g_M + (size_t)i * NB * N_DIM + (size_t)k * NB;
                float* Cp = g_M + (size_t)i * NB * N_DIM + (size_t)(k + 1) * NB;
                float acc[4][4] = {};
                gemm1k<1>(sh, Ap, N_DIM, Bp, N_DIM, acc, NB);
                __syncthreads();
                store1k(Cp, N_DIM, acc, 1);
                __syncthreads();
            }
        }
        grid_bar(bi++);
        // lookahead: diag(k+1) on block 0; syrk-rest (cols >= k+2) on others
        if (bid == 0) {
            diag_factor_invert(k + 1, sh);
        } else {
            const int nrest = (nt - 1) * nt / 2;  // pairs k+2<=j<=i<=31
            for (int t = bid - 1; t < nrest; t += PERS_BLOCKS - 1) {
                int j = k + 2, rem = t;
                while (rem >= (NPAN - j)) { rem -= (NPAN - j); j++; }
                int i = j + rem;
                const float* Ap = g_M + (size_t)i * NB * N_DIM + (size_t)k * NB;
                const float* Bp = g_M + (size_t)j * NB * N_DIM + (size_t)k * NB;
                float* Cp = g_M + (size_t)i * NB * N_DIM + (size_t)j * NB;
                float acc[4][4] = {};
                gemm1k<1>(sh, Ap, N_DIM, Bp, N_DIM, acc, NB);
                __syncthreads();
                store1k(Cp, N_DIM, acc, 1);
                __syncthreads();
            }
        }
        grid_bar(bi++);
    }

    // tail: F/G for all 496 lower tiles (independent; all Linv/L final)
    {
        const int ntiles = NPAN * (NPAN - 1) / 2;
        for (int t = bid; t < ntiles; t += PERS_BLOCKS) {
            int j = 0, rem = t;
            while (rem >= (NPAN - 1 - j)) { rem -= (NPAN - 1 - j); j++; }
            int i = j + 1 + rem;
            fg_tile(sh, i, j);
            __syncthreads();
        }
    }
}

// ---------------- persistent solve (1024 thr, db gemm1k) -------------------
__global__ __launch_bounds__(1024, 1)
void solve_all_kernel(const float* __restrict__ Kb, const float* __restrict__ Phi,
                      const float* __restrict__ a_p, float* __restrict__ out) {
    extern __shared__ float sm[];
    const int bid = blockIdx.x;   // 128
    const int tid = threadIdx.x;  // 1024
    int barIdx = SOLVE_BAR_BASE;

    // X1 = K
    {
        size_t n4 = (size_t)B_DIM * N_DIM / 4;
        const float4* src = reinterpret_cast<const float4*>(Kb);
        float4* dst = reinterpret_cast<float4*>(g_X1);
        for (size_t i = (size_t)bid * 1024 + tid; i < n4;
             i += (size_t)PERS_BLOCKS * 1024)
            dst[i] = src[i];
    }
    grid_bar(barIdx++);

    for (int pass = 0; pass < 2; pass++) {
        // forward: X1 (work) -> X2 (out)
        for (int k = 0; k < NPAN; k++) {
            int ntile = 4 * (NPAN - k);
            if (bid < ntile) {
                int bx = bid >> 2, by = bid & 3;
                const float* A = g_X1 + (size_t)(by * NB) * N_DIM + (size_t)k * NB;
                float acc[4][4] = {};
                if (bx == 0) {
                    gemm1k<1>(sm, A, N_DIM, g_Linv + (size_t)k * NB * NB, NB, acc, NB);
                    store1k(g_X2 + (size_t)(by * NB) * N_DIM + (size_t)k * NB,
                            N_DIM, acc, 0);
                } else {
                    int t = k + bx;
                    gemm1k<1>(sm, A, N_DIM,
                              g_M + (size_t)t * NB * N_DIM + (size_t)k * NB, N_DIM,
                              acc, NB);
                    store1k(g_X1 + (size_t)(by * NB) * N_DIM + (size_t)t * NB,
                            N_DIM, acc, 1);
                }
            }
            grid_bar(barIdx++);
        }
        // backward: X2 (work) -> X3 (out; pass1 accumulates)
        for (int k = NPAN - 1; k >= 0; k--) {
            int ntile = 4 * (k + 1);
            if (bid < ntile) {
                int bx = bid >> 2, by = bid & 3;
                const float* A = g_X2 + (size_t)(by * NB) * N_DIM + (size_t)k * NB;
                float acc[4][4] = {};
                if (bx == k) {
                    gemm1k<0>(sm, A, N_DIM, g_Linv + (size_t)k * NB * NB, NB, acc, NB);
                    store1k(g_X3 + (size_t)(by * NB) * N_DIM + (size_t)k * NB,
                            N_DIM, acc, pass ? 2 : 0);
                } else {
                    gemm1k<0>(sm, A, N_DIM,
                              g_M + (size_t)bx * NB * N_DIM + (size_t)k * NB, N_DIM,
                              acc, NB);
                    store1k(g_X2 + (size_t)(by * NB) * N_DIM + (size_t)bx * NB,
                            N_DIM, acc, 1);
                }
            }
            grid_bar(barIdx++);
        }
        if (pass == 0) {
            // residual: X1 = Kb - c1*X3*Phi - c2*X3 (128 tiles, K=4096)
            int bx = bid >> 2, by = bid & 3;
            int r0 = by * 128, c0 = bx * 128;
            float acc[4][4] = {};
            gemm1k<0>(sm, g_X3 + (size_t)r0 * N_DIM, N_DIM, Phi + c0, N_DIM,
                      acc, N_DIM);
            const float c1 = g_scal[0], c2 = g_scal[1];
            const int ty = tid >> 5, tx = tid & 31;
            #pragma unroll
            for (int i = 0; i < 4; i++) {
                size_t base = (size_t)(r0 + ty * 4 + i) * N_DIM + c0 + tx * 4;
                #pragma unroll
                for (int j = 0; j < 4; j++)
                    g_X1[base + j] = Kb[base + j] - c1 * acc[i][j] - c2 * g_X3[base + j];
            }
            grid_bar(barIdx++);
        }
    }

    // finish: out = X3 row / (a * <X3 row, K row>), 4 rows per block
    {
        float* red = sm;       // 32 warp partials
        float* dshp = sm + 32;
        const float a_val = a_p[0];
        for (int rr = 0; rr < 4; rr++) {
            int row = bid * 4 + rr;
            const float* z = &g_X3[(size_t)row * N_DIM];
            const float* kk = &Kb[(size_t)row * N_DIM];
            float s = 0.0f;
            for (int j = tid; j < N_DIM; j += 1024) s += z[j] * kk[j];
            #pragma unroll
            for (int o = 16; o > 0; o >>= 1)
                s += __shfl_down_sync(0xffffffffu, s, o);
            if ((tid & 31) == 0) red[tid >> 5] = s;
            __syncthreads();
            if (tid == 0) {
                float t = 0.0f;
                #pragma unroll
                for (int w = 0; w < 32; w++) t += red[w];
                dshp[0] = 1.0f / (a_val * t);
            }
            __syncthreads();
            float d = dshp[0];
            for (int j = tid; j < N_DIM; j += 1024)
                out[(size_t)row * N_DIM + j] = z[j] * d;
            __syncthreads();
        }
    }
}

// ---------------- host orchestration --------------------------------------
extern "C" void kernel_launch(void* const* d_in, const int* in_sizes, int n_in,
                              void* d_out, int out_size) {
    // Bind inputs BY SIZE (robust to metadata ordering).
    const float* Kb = nullptr;
    const float* Phi = nullptr;
    const float* v1024a = nullptr;
    const float* v1024b = nullptr;
    const float* a_p = nullptr;
    const float* gam = nullptr;
    for (int i = 0; i < n_in; i++) {
        int sz = in_sizes[i];
        const float* p = (const float*)d_in[i];
        if (sz == N_DIM * N_DIM) Phi = p;
        else if (sz == B_DIM * N_DIM) Kb = p;
        else if (sz == 1024) { if (!v1024a) v1024a = p; else v1024b = p; }
        else if (sz == 1) { if (!a_p) a_p = p; else gam = p; }
    }
    (void)out_size;

    cudaFuncSetAttribute(chol_all_kernel,
                         cudaFuncAttributeMaxDynamicSharedMemorySize, SMEM_CHOL);
    cudaFuncSetAttribute(solve_all_kernel,
                         cudaFuncAttributeMaxDynamicSharedMemorySize, SMEM_G1K);

    scalars_kernel<<<1, 1024>>>(v1024a, v1024b, gam);
    build_M_kernel<<<4096, 256>>>(Phi);

    // blocked Cholesky + tail F/G: ONE persistent launch with lookahead
    chol_all_kernel<<<PERS_BLOCKS, 1024, SMEM_CHOL>>>();

    // solve1 + IR + finish: ONE persistent launch
    solve_all_kernel<<<PERS_BLOCKS, 1024, SMEM_G1K>>>(Kb, Phi, a_p, (float*)d_out);
}